// round 5
// baseline (speedup 1.0000x reference)
#include <cuda_runtime.h>
#include <cuda_bf16.h>
#include <math.h>
#include <stdint.h>

#define B_   1024
#define T_   100
#define XD_  38
#define H_   500
#define ZD_  16
#define L_   3
#define G3H  1500
#define KP   512
#define NP   1536
#define M2   2048
#define MT_  16
#define NT_  12
#define NTILES (MT_*NT_)   // 192
#define CH_  8
#define CHB  16384
#define NCTA 148
#define NTHR 256
#define NBC  7            // max batches per CTA (1024/148 -> 7)
#define SMEMB 132096

// ----------------------------- device scratch --------------------------------
__device__ float g_h_all[M2*KP];
__device__ float g_Gh[(size_t)M2*NP];
__device__ uint8_t g_Abf[(size_t)MT_*2*CH_*CHB];
__device__ uint8_t g_Bbf[(size_t)2*NT_*2*CH_*CHB];
__device__ float g_WihTq[XD_*G3H];
__device__ float g_WihTp[ZD_*G3H];
__device__ float g_uhat[L_*ZD_];
__device__ float g_zprev[B_*ZD_];
__device__ unsigned g_bar_count;
__device__ volatile unsigned g_bar_gen;

// ----------------------------- helpers ---------------------------------------
__device__ __forceinline__ float sigmoidf_(float x){ return 1.0f/(1.0f+expf(-x)); }
__device__ __forceinline__ float softplusf_(float x){ return (x>20.0f)? x : log1pf(expf(x)); }
__device__ __forceinline__ uint32_t swz128(uint32_t off){ return off ^ ((off>>3)&0x70); }

__device__ __forceinline__ size_t a_stage(int mt,int split,int ch){
    return (((size_t)mt*2 + split)*CH_ + ch)*CHB;
}
__device__ __forceinline__ size_t b_stage(int gru,int nt,int split,int ch){
    return ((((size_t)gru*NT_ + nt)*2 + split)*CH_ + ch)*CHB;
}
__device__ __forceinline__ void write_a_split(int m, int k, float v){
    int mt = m>>7, r = m&127, ch = k>>6, c = k&63;
    uint32_t sw = swz128((uint32_t)(r*128 + c*2));
    __nv_bfloat16 hi = __float2bfloat16(v);
    float rem = v - __bfloat162float(hi);
    __nv_bfloat16 lo = __float2bfloat16(rem);
    *(__nv_bfloat16*)(g_Abf + a_stage(mt,0,ch) + sw) = hi;
    *(__nv_bfloat16*)(g_Abf + a_stage(mt,1,ch) + sw) = lo;
}
__device__ __forceinline__ uint32_t smem_u32(const void* p){
    uint32_t a;
    asm("{ .reg .u64 t; cvta.to.shared.u64 t, %1; cvt.u32.u64 %0, t; }" : "=r"(a) : "l"(p));
    return a;
}
__device__ __forceinline__ void cp_async16(uint32_t dst, const void* src){
    asm volatile("cp.async.cg.shared.global [%0], [%1], 16;" :: "r"(dst), "l"(src));
}
__device__ __forceinline__ void cp_commit(){ asm volatile("cp.async.commit_group;" ::: "memory"); }
template<int N>
__device__ __forceinline__ void cp_wait(){ asm volatile("cp.async.wait_group %0;" :: "n"(N) : "memory"); }
__device__ __forceinline__ void ldsm_x4(uint32_t& r0, uint32_t& r1, uint32_t& r2, uint32_t& r3, uint32_t addr){
    asm volatile("ldmatrix.sync.aligned.m8n8.x4.shared.b16 {%0,%1,%2,%3}, [%4];"
                 : "=r"(r0), "=r"(r1), "=r"(r2), "=r"(r3) : "r"(addr));
}
__device__ __forceinline__ void mma_bf16(float* c, const uint32_t* a, const uint32_t* b){
    asm volatile("mma.sync.aligned.m16n8k16.row.col.f32.bf16.bf16.f32 "
                 "{%0,%1,%2,%3}, {%4,%5,%6,%7}, {%8,%9}, {%0,%1,%2,%3};"
                 : "+f"(c[0]), "+f"(c[1]), "+f"(c[2]), "+f"(c[3])
                 : "r"(a[0]), "r"(a[1]), "r"(a[2]), "r"(a[3]), "r"(b[0]), "r"(b[1]));
}

// monotonic grid barrier. fences on both sides give cross-SM visibility (CCTL.IVALL).
__device__ __forceinline__ void grid_barrier(unsigned &gen){
    __syncthreads();
    if (threadIdx.x == 0){
        unsigned my = gen + 1;
        __threadfence();
        unsigned prev = atomicAdd(&g_bar_count, 1u);
        if (prev == my*NCTA - 1){
            __threadfence();
            g_bar_gen = my;
        } else {
            while (g_bar_gen < my) __nanosleep(64);
        }
    }
    gen++;
    __syncthreads();
    __threadfence();
}

// ----------------------------- batch-phase smem layout ------------------------
struct BatchSmem {
    float xs[NBC][40];
    float zp[NBC][16];
    float zc[NBC][16];
    float smu[NBC][16];
    float ssd[NBC][16];
    float hq[NBC][512];
    float hp[NBC][512];
};

// ----------------------------- setup kernels ----------------------------------
__global__ void init_kernel(float* __restrict__ out_ld){
    size_t i = (size_t)blockIdx.x*blockDim.x + threadIdx.x;
    size_t stride = (size_t)gridDim.x*blockDim.x;
    float4* h4 = (float4*)g_h_all;
    for (size_t k=i; k<(size_t)M2*KP/4; k+=stride) h4[k] = make_float4(0,0,0,0);
    uint4* a4 = (uint4*)g_Abf;
    for (size_t k=i; k<sizeof(g_Abf)/16; k+=stride) a4[k] = make_uint4(0,0,0,0);
    for (size_t k=i; k<B_*ZD_; k+=stride) g_zprev[k]=0.f;
    for (size_t k=i; k<B_;     k+=stride) out_ld[k]=0.f;
    if (i == 0){ g_bar_count = 0; g_bar_gen = 0; }
}
__global__ void stage_whh(const float* __restrict__ W, int gru){
    int idx = blockIdx.x*blockDim.x + threadIdx.x;
    if (idx >= G3H*H_) return;
    int n = idx / H_, k = idx - n*H_;
    float v = W[idx];
    int nt = n>>7, r = n&127, ch = k>>6, c = k&63;
    uint32_t sw = swz128((uint32_t)(r*128 + c*2));
    __nv_bfloat16 hi = __float2bfloat16(v);
    float rem = v - __bfloat162float(hi);
    __nv_bfloat16 lo = __float2bfloat16(rem);
    *(__nv_bfloat16*)(g_Bbf + b_stage(gru,nt,0,ch) + sw) = hi;
    *(__nv_bfloat16*)(g_Bbf + b_stage(gru,nt,1,ch) + sw) = lo;
}
__global__ void zero_bbf_pad(){
    // zero only K-pad region (k in [500,512)) of both weight image sets: simplest
    // to zero whole buffer first; done here grid-stride.
    size_t i = (size_t)blockIdx.x*blockDim.x + threadIdx.x;
    size_t stride = (size_t)gridDim.x*blockDim.x;
    uint4* b4 = (uint4*)g_Bbf;
    for (size_t k=i; k<sizeof(g_Bbf)/16; k+=stride) b4[k] = make_uint4(0,0,0,0);
}
__global__ void transpose_wih(const float* __restrict__ W, float* __restrict__ WT, int C){
    int idx = blockIdx.x*blockDim.x + threadIdx.x;
    if (idx < G3H*C){
        int g = idx / C, d = idx - g*C;
        WT[(size_t)d*G3H + g] = W[idx];
    }
}
__global__ void uhat_kernel(const float* __restrict__ fu, const float* __restrict__ fw){
    int k = threadIdx.x;
    if (k < L_){
        float wu=0.f, ww=0.f;
        for (int j=0;j<ZD_;j++){ wu += fw[k*ZD_+j]*fu[k*ZD_+j]; ww += fw[k*ZD_+j]*fw[k*ZD_+j]; }
        float m = -1.0f + softplusf_(wu);
        float scale = (m - wu)/(ww + 1e-6f);
        for (int j=0;j<ZD_;j++) g_uhat[k*ZD_+j] = fu[k*ZD_+j] + scale*fw[k*ZD_+j];
    }
}

// ----------------------------- GEMM tile (device fn) --------------------------
__device__ void gemm_tile(uint8_t* tiles, uint32_t sbase, int mt, int nt, int tid){
    int wid = tid>>5, lane = tid&31;
    int gru = mt>>3;
    int wm = wid & 1, wn = wid >> 1;

    float acc[4][4][4];
#pragma unroll
    for (int i=0;i<4;i++)
#pragma unroll
        for (int j=0;j<4;j++)
#pragma unroll
            for (int c=0;c<4;c++) acc[i][j][c]=0.f;

    int g = lane >> 3, l = lane & 7;
    int a_row = wm*64 + (g&1)*8 + l;
    int a_kb  = (g>>1)*16;
    int b_row = wn*32 + (g>>1)*8 + l;
    int b_kb  = (g&1)*16;

    auto copy_chunk = [&](int ch, int buf){
        const uint8_t* srcs[4] = {
            g_Abf + a_stage(mt,0,ch), g_Abf + a_stage(mt,1,ch),
            g_Bbf + b_stage(gru,nt,0,ch), g_Bbf + b_stage(gru,nt,1,ch)
        };
        uint32_t dbase = sbase + buf*65536;
#pragma unroll
        for (int r=0;r<16;r++){
            int idx = r*256 + tid;
            int img = idx >> 10;
            int off = (idx & 1023)*16;
            cp_async16(dbase + img*16384 + off, srcs[img] + off);
        }
    };

    copy_chunk(0,0); cp_commit();

    for (int ch=0; ch<CH_; ch++){
        if (ch+1 < CH_){ copy_chunk(ch+1,(ch+1)&1); cp_commit(); cp_wait<1>(); }
        else cp_wait<0>();
        __syncthreads();

        uint32_t Ahi_b = sbase + (ch&1)*65536;
        uint32_t Alo_b = Ahi_b + 16384;
        uint32_t Bhi_b = Ahi_b + 32768;
        uint32_t Blo_b = Ahi_b + 49152;

#pragma unroll
        for (int s=0; s<4; s++){
            uint32_t Ah[4][4], Al[4][4], Bh[4][2], Bl[4][2];
            uint32_t a_off = swz128((uint32_t)(a_row*128 + s*32 + a_kb));
            uint32_t b_off = swz128((uint32_t)(b_row*128 + s*32 + b_kb));
#pragma unroll
            for (int mi=0; mi<4; mi++){
                uint32_t ao = a_off + mi*16*128;
                ldsm_x4(Ah[mi][0],Ah[mi][1],Ah[mi][2],Ah[mi][3], Ahi_b + ao);
                ldsm_x4(Al[mi][0],Al[mi][1],Al[mi][2],Al[mi][3], Alo_b + ao);
            }
#pragma unroll
            for (int p=0; p<2; p++){
                uint32_t bo = b_off + p*16*128;
                uint32_t r0,r1,r2,r3;
                ldsm_x4(r0,r1,r2,r3, Bhi_b + bo);
                Bh[2*p][0]=r0; Bh[2*p][1]=r1; Bh[2*p+1][0]=r2; Bh[2*p+1][1]=r3;
                ldsm_x4(r0,r1,r2,r3, Blo_b + bo);
                Bl[2*p][0]=r0; Bl[2*p][1]=r1; Bl[2*p+1][0]=r2; Bl[2*p+1][1]=r3;
            }
#pragma unroll
            for (int mi=0; mi<4; mi++)
#pragma unroll
                for (int ni=0; ni<4; ni++){
                    mma_bf16(acc[mi][ni], Ah[mi], Bh[ni]);
                    mma_bf16(acc[mi][ni], Ah[mi], Bl[ni]);
                    mma_bf16(acc[mi][ni], Al[mi], Bh[ni]);
                }
        }
        __syncthreads();
    }

    int mbase = mt*128 + wm*64;
    int nbase = nt*128 + wn*32;
    int rr = lane>>2, cc = (lane&3)*2;
#pragma unroll
    for (int mi=0; mi<4; mi++){
#pragma unroll
        for (int ni=0; ni<4; ni++){
            int m = mbase + mi*16 + rr;
            int n = nbase + ni*8 + cc;
            *(float2*)&g_Gh[(size_t)m*NP + n]     = make_float2(acc[mi][ni][0], acc[mi][ni][1]);
            *(float2*)&g_Gh[(size_t)(m+8)*NP + n] = make_float2(acc[mi][ni][2], acc[mi][ni][3]);
        }
    }
}

// ----------------------------- persistent kernel ------------------------------
__global__ __launch_bounds__(NTHR)
void persistent_kernel(const float* __restrict__ x, const float* __restrict__ eps,
                       const float* __restrict__ bih_q, const float* __restrict__ bhh_q,
                       const float* __restrict__ Wqm, const float* __restrict__ bqm,
                       const float* __restrict__ Wqs, const float* __restrict__ bqs,
                       const float* __restrict__ bih_p, const float* __restrict__ bhh_p,
                       const float* __restrict__ Wpm, const float* __restrict__ bpm,
                       const float* __restrict__ Wps, const float* __restrict__ bps,
                       const float* __restrict__ fw, const float* __restrict__ fb,
                       float* __restrict__ out_rm, float* __restrict__ out_rs,
                       float* __restrict__ out_z, float* __restrict__ out_mu,
                       float* __restrict__ out_std, float* __restrict__ out_ld){
    extern __shared__ uint8_t smem_raw[];
    uint8_t* tiles = (uint8_t*)(((uintptr_t)smem_raw + 1023) & ~(uintptr_t)1023);
    uint32_t sbase = smem_u32(tiles);
    BatchSmem* bs = (BatchSmem*)tiles;

    int tid = threadIdx.x;
    int cta = blockIdx.x;
    int w = tid>>5, lane = tid&31;
    int nb = (cta < (B_ - (NBC-1)*NCTA)) ? NBC : NBC-1;   // 0..135 -> 7, else 6
    unsigned gen = 0;

    for (int t=0; t<T_; t++){
        // ===================== phase 1: recurrent GEMM =====================
        for (int tile = cta; tile < NTILES; tile += NCTA){
            int mt = tile / NT_;
            int nt = tile - mt*NT_;
            gemm_tile(tiles, sbase, mt, nt, tid);
        }
        grid_barrier(gen);

        // ===================== phase 2: per-batch fused ====================
        // load x rows + zprev
        for (int idx = tid; idx < NBC*XD_; idx += NTHR){
            int r = idx / XD_, d = idx - r*XD_;
            bs->xs[r][d] = (r < nb) ? x[((size_t)(cta + r*NCTA)*T_ + t)*XD_ + d] : 0.f;
        }
        for (int idx = tid; idx < NBC*ZD_; idx += NTHR){
            int r = idx >> 4, d = idx & 15;
            bs->zp[r][d] = (r < nb) ? g_zprev[(cta + r*NCTA)*ZD_ + d] : 0.f;
        }
        __syncthreads();

        // ---- q GRU gates ----
        for (int jj = tid; jj < H_; jj += NTHR){
            float ar[NBC], az[NBC], an[NBC];
#pragma unroll
            for (int r=0;r<NBC;r++){ ar[r]=0.f; az[r]=0.f; an[r]=0.f; }
#pragma unroll 2
            for (int d=0; d<XD_; d++){
                float w0 = g_WihTq[d*G3H + jj];
                float w1 = g_WihTq[d*G3H + H_ + jj];
                float w2 = g_WihTq[d*G3H + 2*H_ + jj];
#pragma unroll
                for (int r=0;r<NBC;r++){
                    float xv = bs->xs[r][d];
                    ar[r] = fmaf(xv, w0, ar[r]);
                    az[r] = fmaf(xv, w1, az[r]);
                    an[r] = fmaf(xv, w2, an[r]);
                }
            }
            float bR = bih_q[jj] + bhh_q[jj];
            float bZ = bih_q[H_+jj] + bhh_q[H_+jj];
            float bN = bih_q[2*H_+jj], bhN = bhh_q[2*H_+jj];
            for (int r=0;r<nb;r++){
                int b = cta + r*NCTA;
                const float* gh = g_Gh + (size_t)b*NP;
                float rr = sigmoidf_(ar[r] + bR + gh[jj]);
                float zz = sigmoidf_(az[r] + bZ + gh[H_+jj]);
                float nn = tanhf    (an[r] + bN + rr*(gh[2*H_+jj] + bhN));
                size_t hi = (size_t)b*KP + jj;
                float hv = (1.f - zz)*nn + zz*g_h_all[hi];
                g_h_all[hi] = hv;
                bs->hq[r][jj] = hv;
                write_a_split(b, jj, hv);
            }
        }
        __syncthreads();

        // ---- mu/std GEMVs (32 outputs per batch, warp-split) ----
        for (int o = w; o < 2*ZD_; o += 8){
            int oj = o & 15;
            const float* Wrow = ((o < ZD_) ? Wqm : Wqs) + (size_t)oj*(H_+ZD_);
            for (int r=0;r<nb;r++){
                float acc = 0.f;
                for (int i=lane; i<H_; i+=32) acc = fmaf(bs->hq[r][i], Wrow[i], acc);
                if (lane < ZD_) acc = fmaf(bs->zp[r][lane], Wrow[H_+lane], acc);
#pragma unroll
                for (int off=16; off; off>>=1) acc += __shfl_down_sync(0xFFFFFFFFu, acc, off);
                if (lane == 0){
                    int b = cta + r*NCTA;
                    size_t oidx = ((size_t)b*T_ + t)*ZD_ + oj;
                    if (o < ZD_){ float mu = acc + bqm[oj]; bs->smu[r][oj] = mu; out_mu[oidx] = mu; }
                    else        { float s = softplusf_(acc + bqs[oj]) + 1e-4f; bs->ssd[r][oj] = s; out_std[oidx] = s; }
                }
            }
        }
        __syncthreads();

        // ---- planar flows (one warp per batch) ----
        if (w < nb){
            int r = w, b = cta + r*NCTA;
            if (lane < ZD_)
                bs->zc[r][lane] = bs->smu[r][lane]
                                + eps[((size_t)b*T_ + t)*ZD_ + lane]*bs->ssd[r][lane];
            __syncwarp();
            if (lane == 0){
                float ld = 0.f;
#pragma unroll
                for (int k=0;k<L_;k++){
                    float dot = 0.f;
                    for (int i=0;i<ZD_;i++) dot = fmaf(bs->zc[r][i], fw[k*ZD_+i], dot);
                    float hh = tanhf(dot + fb[k]);
                    float psiu = 0.f;
                    for (int i=0;i<ZD_;i++){
                        bs->zc[r][i] += g_uhat[k*ZD_+i]*hh;
                        psiu = fmaf((1.f - hh*hh)*fw[k*ZD_+i], g_uhat[k*ZD_+i], psiu);
                    }
                    ld += logf(fabsf(1.f + psiu) + 1e-6f);
                }
                out_ld[b] += ld;
            }
            __syncwarp();
            if (lane < ZD_){
                float zv = bs->zc[r][lane];
                out_z[((size_t)b*T_ + t)*ZD_ + lane] = zv;
                g_zprev[b*ZD_ + lane] = zv;
            }
        }
        __syncthreads();

        // ---- p GRU gates ----
        for (int jj = tid; jj < H_; jj += NTHR){
            float ar[NBC], az[NBC], an[NBC];
#pragma unroll
            for (int r=0;r<NBC;r++){ ar[r]=0.f; az[r]=0.f; an[r]=0.f; }
#pragma unroll
            for (int d=0; d<ZD_; d++){
                float w0 = g_WihTp[d*G3H + jj];
                float w1 = g_WihTp[d*G3H + H_ + jj];
                float w2 = g_WihTp[d*G3H + 2*H_ + jj];
#pragma unroll
                for (int r=0;r<NBC;r++){
                    float zv = bs->zc[r][d];
                    ar[r] = fmaf(zv, w0, ar[r]);
                    az[r] = fmaf(zv, w1, az[r]);
                    an[r] = fmaf(zv, w2, an[r]);
                }
            }
            float bR = bih_p[jj] + bhh_p[jj];
            float bZ = bih_p[H_+jj] + bhh_p[H_+jj];
            float bN = bih_p[2*H_+jj], bhN = bhh_p[2*H_+jj];
            for (int r=0;r<nb;r++){
                int b2 = 1024 + cta + r*NCTA;
                const float* gh = g_Gh + (size_t)b2*NP;
                float rr = sigmoidf_(ar[r] + bR + gh[jj]);
                float zz = sigmoidf_(az[r] + bZ + gh[H_+jj]);
                float nn = tanhf    (an[r] + bN + rr*(gh[2*H_+jj] + bhN));
                size_t hi = (size_t)b2*KP + jj;
                float hv = (1.f - zz)*nn + zz*g_h_all[hi];
                g_h_all[hi] = hv;
                bs->hp[r][jj] = hv;
                write_a_split(b2, jj, hv);
            }
        }
        __syncthreads();

        // ---- reconstruction heads (76 outputs per batch, warp-split) ----
        for (int o = w; o < 2*XD_; o += 8){
            int d = (o < XD_) ? o : o - XD_;
            const float* Wrow = ((o < XD_) ? Wpm : Wps) + (size_t)d*H_;
            for (int r=0;r<nb;r++){
                float acc = 0.f;
                for (int i=lane; i<H_; i+=32) acc = fmaf(bs->hp[r][i], Wrow[i], acc);
#pragma unroll
                for (int off=16; off; off>>=1) acc += __shfl_down_sync(0xFFFFFFFFu, acc, off);
                if (lane == 0){
                    int b = cta + r*NCTA;
                    size_t oidx = ((size_t)b*T_ + t)*XD_ + d;
                    if (o < XD_) out_rm[oidx] = acc + bpm[d];
                    else         out_rs[oidx] = softplusf_(acc + bps[d]) + 1e-4f;
                }
            }
        }
        grid_barrier(gen);
    }
}

// ----------------------------- launcher --------------------------------------
extern "C" void kernel_launch(void* const* d_in, const int* in_sizes, int n_in,
                              void* d_out, int out_size){
    const float* x     = (const float*)d_in[0];
    const float* eps   = (const float*)d_in[1];
    const float* Wih_q = (const float*)d_in[2];
    const float* Whh_q = (const float*)d_in[3];
    const float* bih_q = (const float*)d_in[4];
    const float* bhh_q = (const float*)d_in[5];
    const float* Wqm   = (const float*)d_in[6];
    const float* bqm   = (const float*)d_in[7];
    const float* Wqs   = (const float*)d_in[8];
    const float* bqs   = (const float*)d_in[9];
    const float* Wih_p = (const float*)d_in[10];
    const float* Whh_p = (const float*)d_in[11];
    const float* bih_p = (const float*)d_in[12];
    const float* bhh_p = (const float*)d_in[13];
    const float* Wpm   = (const float*)d_in[14];
    const float* bpm   = (const float*)d_in[15];
    const float* Wps   = (const float*)d_in[16];
    const float* bps   = (const float*)d_in[17];
    const float* fu    = (const float*)d_in[18];
    const float* fw    = (const float*)d_in[19];
    const float* fb    = (const float*)d_in[20];

    float* out = (float*)d_out;
    float* out_rm  = out;
    float* out_rs  = out_rm  + (size_t)B_*T_*XD_;
    float* out_z   = out_rs  + (size_t)B_*T_*XD_;
    float* out_mu  = out_z   + (size_t)B_*T_*ZD_;
    float* out_std = out_mu  + (size_t)B_*T_*ZD_;
    float* out_ld  = out_std + (size_t)B_*T_*ZD_;

    float *WihTq, *WihTp;
    cudaGetSymbolAddress((void**)&WihTq, g_WihTq);
    cudaGetSymbolAddress((void**)&WihTp, g_WihTp);

    cudaFuncSetAttribute(persistent_kernel, cudaFuncAttributeMaxDynamicSharedMemorySize, SMEMB);

    init_kernel<<<1024,256>>>(out_ld);
    zero_bbf_pad<<<1024,256>>>();
    {
        int n = G3H*H_;
        stage_whh<<<(n+255)/256,256>>>(Whh_q, 0);
        stage_whh<<<(n+255)/256,256>>>(Whh_p, 1);
        int nq = G3H*XD_;
        transpose_wih<<<(nq+255)/256,256>>>(Wih_q, WihTq, XD_);
        int np = G3H*ZD_;
        transpose_wih<<<(np+255)/256,256>>>(Wih_p, WihTp, ZD_);
    }
    uhat_kernel<<<1,32>>>(fu, fw);

    persistent_kernel<<<NCTA, NTHR, SMEMB>>>(
        x, eps, bih_q, bhh_q, Wqm, bqm, Wqs, bqs,
        bih_p, bhh_p, Wpm, bpm, Wps, bps, fw, fb,
        out_rm, out_rs, out_z, out_mu, out_std, out_ld);
}

// round 6
// speedup vs baseline: 1.0799x; 1.0799x over previous
#include <cuda_runtime.h>
#include <cuda_fp16.h>
#include <math.h>
#include <stdint.h>

#define B_   1024
#define T_   100
#define XD_  38
#define H_   500
#define ZD_  16
#define L_   3
#define G3H  1500
#define KP   512
#define NP   1536
#define M2   2048
#define MT_  16          // M tiles of 128
#define NT64 24          // N tiles of 64
#define CH_  8           // K chunks of 64 fp16
#define ACHB 16384       // A image bytes per (mt,split,ch): 128 rows x 128B
#define BCHB 8192        // B image bytes per (gru,nt,ch): 64 rows x 128B
#define NBQ  4           // batches per block in fused kernels

// ----------------------------- device scratch --------------------------------
__device__ float   g_h_all[M2*KP];                       // fp32 recurrent state
__device__ float   g_Gh[(size_t)M2*NP];                  // recurrent matmul result
__device__ uint8_t g_Ahl[(size_t)MT_*2*CH_*ACHB];        // A fp16 hi/lo SW128 images
__device__ uint8_t g_Bh [(size_t)2*NT64*CH_*BCHB];       // B fp16 SW128 images
__device__ float   g_WihTq[XD_*G3H];
__device__ float   g_WihTp[ZD_*G3H];
__device__ float   g_uhat[L_*ZD_];

// ----------------------------- helpers ---------------------------------------
__device__ __forceinline__ float sigmoidf_(float x){ return 1.0f/(1.0f+expf(-x)); }
__device__ __forceinline__ float softplusf_(float x){ return (x>20.0f)? x : log1pf(expf(x)); }
__device__ __forceinline__ uint32_t swz128(uint32_t off){ return off ^ ((off>>3)&0x70); }

__device__ __forceinline__ size_t a_stage(int mt,int split,int ch){
    return (((size_t)mt*2 + split)*CH_ + ch)*ACHB;
}
__device__ __forceinline__ size_t b_stage(int gru,int nt,int ch){
    return (((size_t)gru*NT64 + nt)*CH_ + ch)*BCHB;
}
__device__ __forceinline__ void write_a_split(int m, int k, float v){
    int mt = m>>7, r = m&127, ch = k>>6, c = k&63;
    uint32_t sw = swz128((uint32_t)(r*128 + c*2));
    __half hi = __float2half_rn(v);
    __half lo = __float2half_rn(v - __half2float(hi));
    *(__half*)(g_Ahl + a_stage(mt,0,ch) + sw) = hi;
    *(__half*)(g_Ahl + a_stage(mt,1,ch) + sw) = lo;
}
__device__ __forceinline__ uint32_t smem_u32(const void* p){
    uint32_t a;
    asm("{ .reg .u64 t; cvta.to.shared.u64 t, %1; cvt.u32.u64 %0, t; }" : "=r"(a) : "l"(p));
    return a;
}
__device__ __forceinline__ void cp_async16(uint32_t dst, const void* src){
    asm volatile("cp.async.cg.shared.global [%0], [%1], 16;" :: "r"(dst), "l"(src));
}
__device__ __forceinline__ void cp_commit(){ asm volatile("cp.async.commit_group;" ::: "memory"); }
template<int N>
__device__ __forceinline__ void cp_wait(){ asm volatile("cp.async.wait_group %0;" :: "n"(N) : "memory"); }
__device__ __forceinline__ void ldsm_x4(uint32_t& r0, uint32_t& r1, uint32_t& r2, uint32_t& r3, uint32_t addr){
    asm volatile("ldmatrix.sync.aligned.m8n8.x4.shared.b16 {%0,%1,%2,%3}, [%4];"
                 : "=r"(r0), "=r"(r1), "=r"(r2), "=r"(r3) : "r"(addr));
}
__device__ __forceinline__ void mma_fp16(float* c, const uint32_t* a, const uint32_t* b){
    asm volatile("mma.sync.aligned.m16n8k16.row.col.f32.f16.f16.f32 "
                 "{%0,%1,%2,%3}, {%4,%5,%6,%7}, {%8,%9}, {%0,%1,%2,%3};"
                 : "+f"(c[0]), "+f"(c[1]), "+f"(c[2]), "+f"(c[3])
                 : "r"(a[0]), "r"(a[1]), "r"(a[2]), "r"(a[3]), "r"(b[0]), "r"(b[1]));
}

// ----------------------------- setup (exactly 5 launches) --------------------
// launch 1: zero state/images + out_ld + u_hat
__global__ void init_kernel(float* __restrict__ out_ld,
                            const float* __restrict__ fu, const float* __restrict__ fw){
    size_t i = (size_t)blockIdx.x*blockDim.x + threadIdx.x;
    size_t stride = (size_t)gridDim.x*blockDim.x;
    float4* h4 = (float4*)g_h_all;
    for (size_t k=i; k<(size_t)M2*KP/4; k+=stride) h4[k] = make_float4(0,0,0,0);
    uint4* a4 = (uint4*)g_Ahl;
    for (size_t k=i; k<sizeof(g_Ahl)/16; k+=stride) a4[k] = make_uint4(0,0,0,0);
    uint4* b4 = (uint4*)g_Bh;
    for (size_t k=i; k<sizeof(g_Bh)/16; k+=stride) b4[k] = make_uint4(0,0,0,0);
    for (size_t k=i; k<B_; k+=stride) out_ld[k]=0.f;
    if (i < L_){
        int k = (int)i;
        float wu=0.f, ww=0.f;
        for (int j=0;j<ZD_;j++){ wu += fw[k*ZD_+j]*fu[k*ZD_+j]; ww += fw[k*ZD_+j]*fw[k*ZD_+j]; }
        float m = -1.0f + softplusf_(wu);
        float scale = (m - wu)/(ww + 1e-6f);
        for (int j=0;j<ZD_;j++) g_uhat[k*ZD_+j] = fu[k*ZD_+j] + scale*fw[k*ZD_+j];
    }
}
// launches 2,3: stage Whh (fp16 single) into SW128 images
__global__ void stage_whh(const float* __restrict__ W, int gru){
    int idx = blockIdx.x*blockDim.x + threadIdx.x;
    if (idx >= G3H*H_) return;
    int n = idx / H_, k = idx - n*H_;
    int nt = n>>6, r = n&63, ch = k>>6, c = k&63;
    uint32_t sw = swz128((uint32_t)(r*128 + c*2));
    *(__half*)(g_Bh + b_stage(gru,nt,ch) + sw) = __float2half_rn(W[idx]);
}
// launches 4,5: input-projection weight transposes
__global__ void transpose_wih(const float* __restrict__ W, float* __restrict__ WT, int C){
    int idx = blockIdx.x*blockDim.x + threadIdx.x;
    if (idx < G3H*C){
        int g = idx / C, d = idx - g*C;
        WT[(size_t)d*G3H + g] = W[idx];
    }
}

// ----------------------------- fp16 2-pass GEMM (128x64 tiles) ---------------
// Gh[m][n] = sum_k h[m][k]*Whh[n][k]  via  Ahi*B + Alo*B
__global__ __launch_bounds__(256)
void gemm_tc(float* __restrict__ Gh){
    extern __shared__ uint8_t smem_raw[];
    uint8_t* tiles = (uint8_t*)(((uintptr_t)smem_raw + 1023) & ~(uintptr_t)1023);
    uint32_t sbase = smem_u32(tiles);

    int tid = threadIdx.x, wid = tid>>5, lane = tid&31;
    int nt = blockIdx.x;              // 0..23
    int mt = blockIdx.y;              // 0..15
    int gru = mt>>3;
    int wm = wid & 1, wn = wid >> 1;  // warp tile 64(m) x 16(n)

    float acc[4][2][4];
#pragma unroll
    for (int i=0;i<4;i++)
#pragma unroll
        for (int j=0;j<2;j++)
#pragma unroll
            for (int c=0;c<4;c++) acc[i][j][c]=0.f;

    int g = lane >> 3, l = lane & 7;
    int a_row = wm*64 + (g&1)*8 + l;
    int a_kb  = (g>>1)*16;
    int b_row = wn*16 + (g>>1)*8 + l;
    int b_kb  = (g&1)*16;

    // per-chunk: Ahi 16KB @0, Alo 16KB @16384, B 8KB @32768 ; 40KB per buffer
    auto copy_chunk = [&](int ch, int buf){
        const uint8_t* sa0 = g_Ahl + a_stage(mt,0,ch);
        const uint8_t* sa1 = g_Ahl + a_stage(mt,1,ch);
        const uint8_t* sb  = g_Bh  + b_stage(gru,nt,ch);
        uint32_t dbase = sbase + buf*40960;
#pragma unroll
        for (int r=0;r<10;r++){
            int idx = r*256 + tid;          // 0..2559
            if (idx < 1024)       cp_async16(dbase + idx*16,          sa0 + idx*16);
            else if (idx < 2048)  cp_async16(dbase + 16384 + (idx-1024)*16, sa1 + (idx-1024)*16);
            else                  cp_async16(dbase + 32768 + (idx-2048)*16, sb  + (idx-2048)*16);
        }
    };

    copy_chunk(0,0); cp_commit();

    for (int ch=0; ch<CH_; ch++){
        if (ch+1 < CH_){ copy_chunk(ch+1,(ch+1)&1); cp_commit(); cp_wait<1>(); }
        else cp_wait<0>();
        __syncthreads();

        uint32_t Ahi_b = sbase + (ch&1)*40960;
        uint32_t Alo_b = Ahi_b + 16384;
        uint32_t Bb    = Ahi_b + 32768;

#pragma unroll
        for (int s=0; s<4; s++){
            uint32_t Ah[4][4], Al[4][4], Bf[2][2];
            uint32_t a_off = swz128((uint32_t)(a_row*128 + s*32 + a_kb));
            uint32_t b_off = swz128((uint32_t)(b_row*128 + s*32 + b_kb));
#pragma unroll
            for (int mi=0; mi<4; mi++){
                uint32_t ao = a_off + mi*16*128;
                ldsm_x4(Ah[mi][0],Ah[mi][1],Ah[mi][2],Ah[mi][3], Ahi_b + ao);
                ldsm_x4(Al[mi][0],Al[mi][1],Al[mi][2],Al[mi][3], Alo_b + ao);
            }
            {
                uint32_t r0,r1,r2,r3;
                ldsm_x4(r0,r1,r2,r3, Bb + b_off);
                Bf[0][0]=r0; Bf[0][1]=r1; Bf[1][0]=r2; Bf[1][1]=r3;
            }
#pragma unroll
            for (int mi=0; mi<4; mi++)
#pragma unroll
                for (int ni=0; ni<2; ni++){
                    mma_fp16(acc[mi][ni], Ah[mi], Bf[ni]);
                    mma_fp16(acc[mi][ni], Al[mi], Bf[ni]);
                }
        }
        __syncthreads();
    }

    int mbase = mt*128 + wm*64;
    int nbase = nt*64 + wn*16;
    int rr = lane>>2, cc = (lane&3)*2;
#pragma unroll
    for (int mi=0; mi<4; mi++){
#pragma unroll
        for (int ni=0; ni<2; ni++){
            int m = mbase + mi*16 + rr;
            int n = nbase + ni*8 + cc;
            *(float2*)&Gh[(size_t)m*NP + n]     = make_float2(acc[mi][ni][0], acc[mi][ni][1]);
            *(float2*)&Gh[(size_t)(m+8)*NP + n] = make_float2(acc[mi][ni][2], acc[mi][ni][3]);
        }
    }
}

// ----------------------------- q gates + z step fused ------------------------
__global__ __launch_bounds__(128)
void qz_fused(const float* __restrict__ x, const float* __restrict__ eps,
              const float* __restrict__ bih_q, const float* __restrict__ bhh_q,
              const float* __restrict__ Wqm, const float* __restrict__ bqm,
              const float* __restrict__ Wqs, const float* __restrict__ bqs,
              const float* __restrict__ fw, const float* __restrict__ fb,
              float* __restrict__ h_all,
              float* __restrict__ out_z, float* __restrict__ out_mu,
              float* __restrict__ out_std, float* __restrict__ out_ld, int t){
    __shared__ float xs[NBQ][XD_+2];
    __shared__ float hq[NBQ][512];
    __shared__ float zp[NBQ][16], zc[NBQ][16], smu[NBQ][16], ssd[NBQ][16];
    int b0 = blockIdx.x * NBQ;
    int tid = threadIdx.x, w = tid>>5, lane = tid&31;

    for (int idx=tid; idx<NBQ*XD_; idx+=128){
        int r = idx / XD_, d = idx - r*XD_;
        xs[r][d] = x[((size_t)(b0+r)*T_ + t)*XD_ + d];
    }
    if (tid < NBQ*ZD_){
        int r = tid >> 4, d = tid & 15;
        zp[r][d] = (t==0) ? 0.f : out_z[((size_t)(b0+r)*T_ + (t-1))*ZD_ + d];
    }
    __syncthreads();

    // q GRU gates (j strided over 128 threads)
    for (int j = tid; j < H_; j += 128){
        float ar[NBQ], az[NBQ], an[NBQ];
#pragma unroll
        for (int r=0;r<NBQ;r++){ ar[r]=0.f; az[r]=0.f; an[r]=0.f; }
#pragma unroll 2
        for (int d=0; d<XD_; d++){
            float w0 = g_WihTq[d*G3H + j];
            float w1 = g_WihTq[d*G3H + H_ + j];
            float w2 = g_WihTq[d*G3H + 2*H_ + j];
#pragma unroll
            for (int r=0;r<NBQ;r++){
                float xv = xs[r][d];
                ar[r] = fmaf(xv, w0, ar[r]);
                az[r] = fmaf(xv, w1, az[r]);
                an[r] = fmaf(xv, w2, an[r]);
            }
        }
        float bR = bih_q[j] + bhh_q[j];
        float bZ = bih_q[H_+j] + bhh_q[H_+j];
        float bN = bih_q[2*H_+j], bhN = bhh_q[2*H_+j];
#pragma unroll
        for (int r=0;r<NBQ;r++){
            int b = b0 + r;
            const float* gh = g_Gh + (size_t)b*NP;
            float rr = sigmoidf_(ar[r] + bR + gh[j]);
            float zz = sigmoidf_(az[r] + bZ + gh[H_+j]);
            float nn = tanhf    (an[r] + bN + rr*(gh[2*H_+j] + bhN));
            size_t hi = (size_t)b*KP + j;
            float hv = (1.f - zz)*nn + zz*h_all[hi];
            h_all[hi] = hv;
            hq[r][j] = hv;
            write_a_split(b, j, hv);
        }
    }
    __syncthreads();

    // mu/std GEMVs: 32 outputs x NBQ batches, warp-split
    for (int k=0; k<8; k++){
        int o = w + 4*k;                 // 0..31
        int oj = o & 15;
        const float* Wrow = ((o < ZD_) ? Wqm : Wqs) + (size_t)oj*(H_+ZD_);
#pragma unroll
        for (int r=0;r<NBQ;r++){
            float acc = 0.f;
            for (int i=lane; i<H_; i+=32) acc = fmaf(hq[r][i], Wrow[i], acc);
            if (lane < ZD_) acc = fmaf(zp[r][lane], Wrow[H_+lane], acc);
#pragma unroll
            for (int off=16; off; off>>=1) acc += __shfl_down_sync(0xFFFFFFFFu, acc, off);
            if (lane == 0){
                size_t oidx = ((size_t)(b0+r)*T_ + t)*ZD_ + oj;
                if (o < ZD_){ float mu = acc + bqm[oj]; smu[r][oj] = mu; out_mu[oidx] = mu; }
                else        { float s = softplusf_(acc + bqs[oj]) + 1e-4f; ssd[r][oj] = s; out_std[oidx] = s; }
            }
        }
    }
    __syncthreads();

    // planar flows: warp w handles batch w
    {
        int r = w, b = b0 + r;
        if (lane < ZD_)
            zc[r][lane] = smu[r][lane] + eps[((size_t)b*T_ + t)*ZD_ + lane]*ssd[r][lane];
        __syncwarp();
        if (lane == 0){
            float ld = 0.f;
#pragma unroll
            for (int k=0;k<L_;k++){
                float dot = 0.f;
                for (int i=0;i<ZD_;i++) dot = fmaf(zc[r][i], fw[k*ZD_+i], dot);
                float hh = tanhf(dot + fb[k]);
                float psiu = 0.f;
                for (int i=0;i<ZD_;i++){
                    zc[r][i] += g_uhat[k*ZD_+i]*hh;
                    psiu = fmaf((1.f - hh*hh)*fw[k*ZD_+i], g_uhat[k*ZD_+i], psiu);
                }
                ld += logf(fabsf(1.f + psiu) + 1e-6f);
            }
            out_ld[b] += ld;
        }
        __syncwarp();
        if (lane < ZD_)
            out_z[((size_t)b*T_ + t)*ZD_ + lane] = zc[r][lane];
    }
}

// ----------------------------- p gates + reconstruction ----------------------
__global__ __launch_bounds__(128)
void p_fused(const float* __restrict__ z_t,
             const float* __restrict__ bih_p, const float* __restrict__ bhh_p,
             float* __restrict__ h_all,
             const float* __restrict__ Wpm, const float* __restrict__ bpm,
             const float* __restrict__ Wps, const float* __restrict__ bps,
             float* __restrict__ out_rm, float* __restrict__ out_rs, int t){
    __shared__ float zs[NBQ][ZD_];
    __shared__ float hp[NBQ][512];
    int b0 = blockIdx.x * NBQ;
    int tid = threadIdx.x, w = tid>>5, lane = tid&31;

    if (tid < NBQ*ZD_){
        int r = tid >> 4, d = tid & 15;
        zs[r][d] = z_t[((size_t)(b0+r)*T_ + t)*ZD_ + d];
    }
    __syncthreads();

    for (int j = tid; j < H_; j += 128){
        float ar[NBQ], az[NBQ], an[NBQ];
#pragma unroll
        for (int r=0;r<NBQ;r++){ ar[r]=0.f; az[r]=0.f; an[r]=0.f; }
#pragma unroll
        for (int d=0; d<ZD_; d++){
            float w0 = g_WihTp[d*G3H + j];
            float w1 = g_WihTp[d*G3H + H_ + j];
            float w2 = g_WihTp[d*G3H + 2*H_ + j];
#pragma unroll
            for (int r=0;r<NBQ;r++){
                float zv = zs[r][d];
                ar[r] = fmaf(zv, w0, ar[r]);
                az[r] = fmaf(zv, w1, az[r]);
                an[r] = fmaf(zv, w2, an[r]);
            }
        }
        float bR = bih_p[j] + bhh_p[j];
        float bZ = bih_p[H_+j] + bhh_p[H_+j];
        float bN = bih_p[2*H_+j], bhN = bhh_p[2*H_+j];
#pragma unroll
        for (int r=0;r<NBQ;r++){
            int b2 = 1024 + b0 + r;
            const float* gh = g_Gh + (size_t)b2*NP;
            float rr = sigmoidf_(ar[r] + bR + gh[j]);
            float zz = sigmoidf_(az[r] + bZ + gh[H_+j]);
            float nn = tanhf    (an[r] + bN + rr*(gh[2*H_+j] + bhN));
            size_t hi = (size_t)b2*KP + j;
            float hv = (1.f - zz)*nn + zz*h_all[hi];
            h_all[hi] = hv;
            hp[r][j] = hv;
            write_a_split(b2, j, hv);
        }
    }
    __syncthreads();

    // reconstruction heads: 76 outputs x NBQ batches, warp-split
    for (int o = w; o < 2*XD_; o += 4){
        int d = (o < XD_) ? o : o - XD_;
        const float* Wrow = ((o < XD_) ? Wpm : Wps) + (size_t)d*H_;
#pragma unroll
        for (int r=0;r<NBQ;r++){
            float acc = 0.f;
            for (int i=lane; i<H_; i+=32) acc = fmaf(hp[r][i], Wrow[i], acc);
#pragma unroll
            for (int off=16; off; off>>=1) acc += __shfl_down_sync(0xFFFFFFFFu, acc, off);
            if (lane == 0){
                size_t oidx = ((size_t)(b0+r)*T_ + t)*XD_ + d;
                if (o < XD_) out_rm[oidx] = acc + bpm[d];
                else         out_rs[oidx] = softplusf_(acc + bps[d]) + 1e-4f;
            }
        }
    }
}

// ----------------------------- launcher --------------------------------------
extern "C" void kernel_launch(void* const* d_in, const int* in_sizes, int n_in,
                              void* d_out, int out_size){
    const float* x     = (const float*)d_in[0];
    const float* eps   = (const float*)d_in[1];
    const float* Wih_q = (const float*)d_in[2];
    const float* Whh_q = (const float*)d_in[3];
    const float* bih_q = (const float*)d_in[4];
    const float* bhh_q = (const float*)d_in[5];
    const float* Wqm   = (const float*)d_in[6];
    const float* bqm   = (const float*)d_in[7];
    const float* Wqs   = (const float*)d_in[8];
    const float* bqs   = (const float*)d_in[9];
    const float* Wih_p = (const float*)d_in[10];
    const float* Whh_p = (const float*)d_in[11];
    const float* bih_p = (const float*)d_in[12];
    const float* bhh_p = (const float*)d_in[13];
    const float* Wpm   = (const float*)d_in[14];
    const float* bpm   = (const float*)d_in[15];
    const float* Wps   = (const float*)d_in[16];
    const float* bps   = (const float*)d_in[17];
    const float* fu    = (const float*)d_in[18];
    const float* fw    = (const float*)d_in[19];
    const float* fb    = (const float*)d_in[20];

    float* out = (float*)d_out;
    float* out_rm  = out;
    float* out_rs  = out_rm  + (size_t)B_*T_*XD_;
    float* out_z   = out_rs  + (size_t)B_*T_*XD_;
    float* out_mu  = out_z   + (size_t)B_*T_*ZD_;
    float* out_std = out_mu  + (size_t)B_*T_*ZD_;
    float* out_ld  = out_std + (size_t)B_*T_*ZD_;

    float *h_all, *Gh, *WihTq, *WihTp;
    cudaGetSymbolAddress((void**)&h_all, g_h_all);
    cudaGetSymbolAddress((void**)&Gh,    g_Gh);
    cudaGetSymbolAddress((void**)&WihTq, g_WihTq);
    cudaGetSymbolAddress((void**)&WihTp, g_WihTp);

    cudaFuncSetAttribute(gemm_tc, cudaFuncAttributeMaxDynamicSharedMemorySize, 84992);

    // exactly 5 setup launches -> first gemm_tc is launch #6 (ncu -s 5 -c 1 target)
    init_kernel<<<1024,256>>>(out_ld, fu, fw);                       // 1
    {
        int n = G3H*H_;
        stage_whh<<<(n+255)/256,256>>>(Whh_q, 0);                    // 2
        stage_whh<<<(n+255)/256,256>>>(Whh_p, 1);                    // 3
        int nq = G3H*XD_;
        transpose_wih<<<(nq+255)/256,256>>>(Wih_q, WihTq, XD_);      // 4
        int np = G3H*ZD_;
        transpose_wih<<<(np+255)/256,256>>>(Wih_p, WihTp, ZD_);      // 5
    }

    dim3 gemm_grid(NT64, MT_);          // 24 x 16 = 384 CTAs
    int nblk = B_/NBQ;                  // 256 blocks

    for (int t=0; t<T_; t++){
        gemm_tc<<<gemm_grid,256,84992>>>(Gh);
        qz_fused<<<nblk,128>>>(x, eps, bih_q, bhh_q, Wqm, bqm, Wqs, bqs, fw, fb,
                               h_all, out_z, out_mu, out_std, out_ld, t);
        p_fused<<<nblk,128>>>(out_z, bih_p, bhh_p, h_all,
                              Wpm, bpm, Wps, bps, out_rm, out_rs, t);
    }
}

// round 7
// speedup vs baseline: 1.4571x; 1.3492x over previous
#include <cuda_runtime.h>
#include <cuda_fp16.h>
#include <math.h>
#include <stdint.h>

#define B_   1024
#define T_   100
#define XD_  38
#define H_   500
#define ZD_  16
#define L_   3
#define G3H  1500
#define HP   512          // padded hidden
#define NG   1536         // 3*512 padded gate dim (Gx columns)
#define MT_G 16           // gru M tiles (64 batch rows each)
#define NT_G 8            // gru N tiles (64 hidden each)
#define CH_  8            // K chunks of 64
#define AIMG 8192         // gru A image: 64 rows x 128B
#define BIMG 8192         // B image: 64 rows x 128B
#define GXMT 800          // (B*T)/128
#define GXNT 24           // 1536/64
#define SMEM_GRU 100608
#define SMEM_GX  41984

// ----------------------------- device scratch --------------------------------
__device__ __align__(1024) float   g_h[(size_t)2*B_*HP];            // 4 MB (rows 0..1023 hq, 1024.. hp)
__device__ __align__(1024) uint8_t g_Ah[(size_t)2*MT_G*2*CH_*AIMG]; // 4 MB  [gru][mt][split][ch]
__device__ __align__(1024) uint8_t g_Bw[(size_t)2*NT_G*3*CH_*BIMG]; // 3 MB  [gru][nt][gate][ch]
__device__ __align__(1024) uint8_t g_Ax[(size_t)GXMT*2*16384];      // 25.6 MB [mt][split]
__device__ __align__(1024) uint8_t g_Bx[(size_t)GXNT*BIMG];         // 192 KB [nt]
__device__ __align__(1024) __half  g_Gx[(size_t)B_*T_*NG];          // 315 MB
__device__ float g_uhat[L_*ZD_];

// ----------------------------- helpers ---------------------------------------
__device__ __forceinline__ float sigmoidf_(float x){ return 1.0f/(1.0f+expf(-x)); }
__device__ __forceinline__ float softplusf_(float x){ return (x>20.0f)? x : log1pf(expf(x)); }
__device__ __forceinline__ uint32_t swz128(uint32_t off){ return off ^ ((off>>3)&0x70); }

__device__ __forceinline__ size_t a_img(int gru,int mt,int split,int ch){
    return ((((size_t)gru*MT_G + mt)*2 + split)*CH_ + ch)*AIMG;
}
__device__ __forceinline__ size_t b_img(int gru,int nt,int gate,int ch){
    return ((((size_t)gru*NT_G + nt)*3 + gate)*CH_ + ch)*BIMG;
}
__device__ __forceinline__ uint32_t smem_u32(const void* p){
    uint32_t a;
    asm("{ .reg .u64 t; cvta.to.shared.u64 t, %1; cvt.u32.u64 %0, t; }" : "=r"(a) : "l"(p));
    return a;
}
__device__ __forceinline__ void cp_async16(uint32_t dst, const void* src){
    asm volatile("cp.async.cg.shared.global [%0], [%1], 16;" :: "r"(dst), "l"(src));
}
__device__ __forceinline__ void cp_commit(){ asm volatile("cp.async.commit_group;" ::: "memory"); }
template<int N>
__device__ __forceinline__ void cp_wait(){ asm volatile("cp.async.wait_group %0;" :: "n"(N) : "memory"); }
__device__ __forceinline__ void ldsm_x4(uint32_t& r0, uint32_t& r1, uint32_t& r2, uint32_t& r3, uint32_t addr){
    asm volatile("ldmatrix.sync.aligned.m8n8.x4.shared.b16 {%0,%1,%2,%3}, [%4];"
                 : "=r"(r0), "=r"(r1), "=r"(r2), "=r"(r3) : "r"(addr));
}
__device__ __forceinline__ void mma_fp16(float* c, const uint32_t* a, const uint32_t* b){
    asm volatile("mma.sync.aligned.m16n8k16.row.col.f32.f16.f16.f32 "
                 "{%0,%1,%2,%3}, {%4,%5,%6,%7}, {%8,%9}, {%0,%1,%2,%3};"
                 : "+f"(c[0]), "+f"(c[1]), "+f"(c[2]), "+f"(c[3])
                 : "r"(a[0]), "r"(a[1]), "r"(a[2]), "r"(a[3]), "r"(b[0]), "r"(b[1]));
}

// ----------------------------- setup launch 1: init --------------------------
__global__ void init_kernel(float* __restrict__ out_ld,
                            const float* __restrict__ fu, const float* __restrict__ fw){
    size_t i = (size_t)blockIdx.x*blockDim.x + threadIdx.x;
    size_t stride = (size_t)gridDim.x*blockDim.x;
    float4* h4 = (float4*)g_h;
    for (size_t k=i; k<sizeof(g_h)/16;  k+=stride) h4[k] = make_float4(0,0,0,0);
    uint4* p;
    p = (uint4*)g_Ah; for (size_t k=i; k<sizeof(g_Ah)/16; k+=stride) p[k] = make_uint4(0,0,0,0);
    p = (uint4*)g_Bw; for (size_t k=i; k<sizeof(g_Bw)/16; k+=stride) p[k] = make_uint4(0,0,0,0);
    p = (uint4*)g_Ax; for (size_t k=i; k<sizeof(g_Ax)/16; k+=stride) p[k] = make_uint4(0,0,0,0);
    p = (uint4*)g_Bx; for (size_t k=i; k<sizeof(g_Bx)/16; k+=stride) p[k] = make_uint4(0,0,0,0);
    for (size_t k=i; k<B_; k+=stride) out_ld[k]=0.f;
    if (i < L_){
        int k = (int)i;
        float wu=0.f, ww=0.f;
        for (int j=0;j<ZD_;j++){ wu += fw[k*ZD_+j]*fu[k*ZD_+j]; ww += fw[k*ZD_+j]*fw[k*ZD_+j]; }
        float m = -1.0f + softplusf_(wu);
        float scale = (m - wu)/(ww + 1e-6f);
        for (int j=0;j<ZD_;j++) g_uhat[k*ZD_+j] = fu[k*ZD_+j] + scale*fw[k*ZD_+j];
    }
}

// ----------------------------- setup launch 2: stage both Whh ----------------
__global__ void stage_whh(const float* __restrict__ Wq, const float* __restrict__ Wp){
    int idx = blockIdx.x*blockDim.x + threadIdx.x;
    if (idx >= 2*G3H*H_) return;
    int gru = idx / (G3H*H_);
    int rem = idx - gru*(G3H*H_);
    int n = rem / H_, k = rem - n*H_;
    float v = (gru ? Wp : Wq)[n*H_ + k];
    int gate = n / 500, j = n - gate*500;
    int nt = j>>6, r = j&63, ch = k>>6, c = k&63;
    *(__half*)(g_Bw + b_img(gru,nt,gate,ch) + swz128((uint32_t)(r*128 + c*2))) = __float2half_rn(v);
}

// ----------------------------- setup launch 3: stage x (split) + Wih_q -------
__global__ void stage_x_wih(const float* __restrict__ x, const float* __restrict__ Wih_q){
    int idx = blockIdx.x*blockDim.x + threadIdx.x;
    const int NX = B_*T_*XD_;
    if (idx < NX){
        int m = idx / XD_, d = idx - m*XD_;          // m = b*T + t
        float v = x[idx];
        int mt = m>>7, r = m&127;
        uint32_t sw = swz128((uint32_t)(r*128 + d*2));
        __half hi = __float2half_rn(v);
        __half lo = __float2half_rn(v - __half2float(hi));
        *(__half*)(g_Ax + (size_t)(mt*2+0)*16384 + sw) = hi;
        *(__half*)(g_Ax + (size_t)(mt*2+1)*16384 + sw) = lo;
    } else if (idx < NX + G3H*XD_){
        int e = idx - NX;
        int n = e / XD_, d = e - n*XD_;
        int gate = n / 500, j = n - gate*500;
        int ni = gate*512 + j;
        int nt = ni>>6, r = ni&63;
        *(__half*)(g_Bx + (size_t)nt*BIMG + swz128((uint32_t)(r*128 + d*2))) =
            __float2half_rn(Wih_q[n*XD_ + d]);
    }
}

// ----------------------------- setup launch 4: Gx = x @ Wih_q^T + bias -------
__global__ __launch_bounds__(256)
void gx_gemm(const float* __restrict__ bih, const float* __restrict__ bhh){
    extern __shared__ uint8_t smem_raw[];
    uint8_t* tiles = (uint8_t*)(((uintptr_t)smem_raw + 1023) & ~(uintptr_t)1023);
    uint32_t sbase = smem_u32(tiles);
    int tid = threadIdx.x, wid = tid>>5, lane = tid&31;
    int nt = blockIdx.x, mt = blockIdx.y;
    int wm = wid & 1, wn = wid >> 1;

    // copy single chunk: Ahi 16KB, Alo 16KB, B 8KB
    {
        const uint8_t* sa0 = g_Ax + (size_t)(mt*2+0)*16384;
        const uint8_t* sa1 = g_Ax + (size_t)(mt*2+1)*16384;
        const uint8_t* sb  = g_Bx + (size_t)nt*BIMG;
#pragma unroll
        for (int r=0;r<10;r++){
            int idx = r*256 + tid;
            if (idx < 1024)      cp_async16(sbase + idx*16, sa0 + idx*16);
            else if (idx < 2048) cp_async16(sbase + 16384 + (idx-1024)*16, sa1 + (idx-1024)*16);
            else                 cp_async16(sbase + 32768 + (idx-2048)*16, sb + (idx-2048)*16);
        }
    }
    cp_commit(); cp_wait<0>(); __syncthreads();

    float acc[4][2][4];
#pragma unroll
    for (int i=0;i<4;i++)
#pragma unroll
        for (int j=0;j<2;j++)
#pragma unroll
            for (int c=0;c<4;c++) acc[i][j][c]=0.f;

    int g = lane >> 3, l = lane & 7;
    int a_row = wm*64 + (g&1)*8 + l;
    int a_kb  = (g>>1)*16;
    int b_row = wn*16 + (g>>1)*8 + l;
    int b_kb  = (g&1)*16;

#pragma unroll
    for (int s=0; s<4; s++){
        uint32_t Ah[4][4], Al[4][4], Bf[2][2];
        uint32_t a_off = swz128((uint32_t)(a_row*128 + s*32 + a_kb));
        uint32_t b_off = swz128((uint32_t)(b_row*128 + s*32 + b_kb));
#pragma unroll
        for (int mi=0; mi<4; mi++){
            uint32_t ao = a_off + mi*2048;
            ldsm_x4(Ah[mi][0],Ah[mi][1],Ah[mi][2],Ah[mi][3], sbase + ao);
            ldsm_x4(Al[mi][0],Al[mi][1],Al[mi][2],Al[mi][3], sbase + 16384 + ao);
        }
        {
            uint32_t r0,r1,r2,r3;
            ldsm_x4(r0,r1,r2,r3, sbase + 32768 + b_off);
            Bf[0][0]=r0; Bf[0][1]=r1; Bf[1][0]=r2; Bf[1][1]=r3;
        }
#pragma unroll
        for (int mi=0; mi<4; mi++)
#pragma unroll
            for (int ni=0; ni<2; ni++){
                mma_fp16(acc[mi][ni], Ah[mi], Bf[ni]);
                mma_fp16(acc[mi][ni], Al[mi], Bf[ni]);
            }
    }

    int rr = lane>>2, cc = (lane&3)*2;
#pragma unroll
    for (int mi=0; mi<4; mi++){
#pragma unroll
        for (int ni=0; ni<2; ni++){
#pragma unroll
            for (int hh=0; hh<2; hh++){
                int m = mt*128 + wm*64 + mi*16 + hh*8 + rr;
                int n = nt*64 + wn*16 + ni*8 + cc;
                int gate = n>>9, j = n&511;
                float v0 = acc[mi][ni][hh*2+0];
                float v1 = acc[mi][ni][hh*2+1];
                if (j+1 < 500){
                    float b0 = bih[gate*500+j]   + (gate<2 ? bhh[gate*500+j]   : 0.f);
                    float b1 = bih[gate*500+j+1] + (gate<2 ? bhh[gate*500+j+1] : 0.f);
                    v0 += b0; v1 += b1;
                }
                *(__half2*)&g_Gx[(size_t)m*NG + n] = __floats2half2_rn(v0, v1);
            }
        }
    }
}

// ----------------------------- fused GRU step (GEMM + combine) ---------------
// gru=0 (q): gate preactivations xw come from g_Gx (biases included).
// gru=1 (p): xw computed inline from z_t and Wih_p.
__global__ __launch_bounds__(256)
void gru_step(int gru, int t,
              const float* __restrict__ out_z,
              const float* __restrict__ Wihp,
              const float* __restrict__ bihp, const float* __restrict__ bhhp,
              const float* __restrict__ bhhq){
    extern __shared__ uint8_t smem_raw[];
    uint8_t* tiles = (uint8_t*)(((uintptr_t)smem_raw + 1023) & ~(uintptr_t)1023);
    uint32_t sbase = smem_u32(tiles);
    float* zzS  = (float*)(tiles + 81920);            // p: [64][17]
    float* wpS  = (float*)(tiles + 86272);            // p: [16][192]
    float* bspS = (float*)(tiles + 98560);            // p: [4][64]
    float* bnnS = (float*)(tiles + 81920);            // q: [64]

    int tid = threadIdx.x, wid = tid>>5, lane = tid&31;
    int nt = blockIdx.x, mt = blockIdx.y;
    int wm = wid & 1, wn = wid >> 1;

    auto copy_chunk = [&](int ch, int buf){
        const uint8_t* srcs[5] = {
            g_Ah + a_img(gru,mt,0,ch), g_Ah + a_img(gru,mt,1,ch),
            g_Bw + b_img(gru,nt,0,ch), g_Bw + b_img(gru,nt,1,ch), g_Bw + b_img(gru,nt,2,ch)
        };
        uint32_t dbase = sbase + buf*40960;
#pragma unroll
        for (int r=0;r<10;r++){
            int idx = r*256 + tid;           // 0..2559
            int img = idx >> 9;              // 512 16B-units per 8KB image
            int off = (idx & 511)*16;
            cp_async16(dbase + img*8192 + off, srcs[img] + off);
        }
    };

    copy_chunk(0,0); cp_commit();

    // stage epilogue extras
    if (!gru){
        if (tid < 64){
            int j = nt*64 + tid;
            bnnS[tid] = (j < 500) ? bhhq[1000 + j] : 0.f;
        }
    } else {
        for (int idx = tid; idx < 64*ZD_; idx += 256){
            int r = idx >> 4, d = idx & 15;
            int b = mt*64 + r;
            zzS[r*17 + d] = out_z[((size_t)b*T_ + t)*ZD_ + d];
        }
        for (int idx = tid; idx < ZD_*192; idx += 256){
            int d = idx & 15, col = idx >> 4;        // col = g*64 + jj
            int gg = col >> 6, jj = col & 63;
            int j = nt*64 + jj;
            wpS[d*192 + col] = (j < 500) ? Wihp[((size_t)(gg*500 + j))*ZD_ + d] : 0.f;
        }
        if (tid < 256){
            int q4 = tid >> 6, jj = tid & 63;
            int j = nt*64 + jj;
            float v = 0.f;
            if (j < 500){
                if (q4 == 0) v = bihp[j]       + bhhp[j];
                else if (q4 == 1) v = bihp[500+j]  + bhhp[500+j];
                else if (q4 == 2) v = bihp[1000+j];
                else v = bhhp[1000+j];
            }
            bspS[q4*64 + jj] = v;
        }
    }
    __syncthreads();

    float acc[3][2][2][4];
#pragma unroll
    for (int a=0;a<3;a++)
#pragma unroll
        for (int i=0;i<2;i++)
#pragma unroll
            for (int j=0;j<2;j++)
#pragma unroll
                for (int c=0;c<4;c++) acc[a][i][j][c]=0.f;

    int g = lane >> 3, l = lane & 7;
    int a_row = wm*32 + (g&1)*8 + l;
    int a_kb  = (g>>1)*16;
    int b_row = wn*16 + (g>>1)*8 + l;
    int b_kb  = (g&1)*16;

    for (int ch=0; ch<CH_; ch++){
        if (ch+1 < CH_){ copy_chunk(ch+1,(ch+1)&1); cp_commit(); cp_wait<1>(); }
        else cp_wait<0>();
        __syncthreads();

        uint32_t Ahi_b = sbase + (ch&1)*40960;
        uint32_t Alo_b = Ahi_b + 8192;
        uint32_t Bb    = Ahi_b + 16384;

#pragma unroll
        for (int s=0; s<4; s++){
            uint32_t Ah[2][4], Al[2][4], Bf[3][2][2];
            uint32_t a_off = swz128((uint32_t)(a_row*128 + s*32 + a_kb));
            uint32_t b_off = swz128((uint32_t)(b_row*128 + s*32 + b_kb));
#pragma unroll
            for (int mi=0; mi<2; mi++){
                uint32_t ao = a_off + mi*2048;
                ldsm_x4(Ah[mi][0],Ah[mi][1],Ah[mi][2],Ah[mi][3], Ahi_b + ao);
                ldsm_x4(Al[mi][0],Al[mi][1],Al[mi][2],Al[mi][3], Alo_b + ao);
            }
#pragma unroll
            for (int g3=0; g3<3; g3++){
                uint32_t r0,r1,r2,r3;
                ldsm_x4(r0,r1,r2,r3, Bb + g3*8192 + b_off);
                Bf[g3][0][0]=r0; Bf[g3][0][1]=r1; Bf[g3][1][0]=r2; Bf[g3][1][1]=r3;
            }
#pragma unroll
            for (int g3=0; g3<3; g3++)
#pragma unroll
                for (int mi=0; mi<2; mi++)
#pragma unroll
                    for (int ni=0; ni<2; ni++){
                        mma_fp16(acc[g3][mi][ni], Ah[mi], Bf[g3][ni]);
                        mma_fp16(acc[g3][mi][ni], Al[mi], Bf[g3][ni]);
                    }
        }
        __syncthreads();
    }

    // -------- epilogue: GRU combine in registers --------
    int rr = lane>>2, cc = (lane&3)*2;
#pragma unroll
    for (int mi=0; mi<2; mi++){
#pragma unroll
        for (int hh=0; hh<2; hh++){
            int mrow = wm*32 + mi*16 + hh*8 + rr;     // [0,64)
            int b = mt*64 + mrow;
            float zr[ZD_];
            if (gru){
#pragma unroll
                for (int d=0; d<ZD_; d++) zr[d] = zzS[mrow*17 + d];
            }
#pragma unroll
            for (int ni=0; ni<2; ni++){
                int jj = wn*16 + ni*8 + cc;           // [0,64)
                int j = nt*64 + jj;
                if (j >= 500) continue;               // pairs never straddle 500
                float xw0[3], xw1[3];
                if (!gru){
                    size_t base = ((size_t)b*T_ + t)*NG + j;
#pragma unroll
                    for (int g3=0; g3<3; g3++){
                        __half2 hv = *(const __half2*)&g_Gx[base + g3*512];
                        xw0[g3] = __low2float(hv);
                        xw1[g3] = __high2float(hv);
                    }
                } else {
#pragma unroll
                    for (int g3=0; g3<3; g3++){
                        float s0 = bspS[g3*64 + jj];
                        float s1 = bspS[g3*64 + jj + 1];
#pragma unroll
                        for (int d=0; d<ZD_; d++){
                            float zv = zr[d];
                            s0 = fmaf(zv, wpS[d*192 + g3*64 + jj],     s0);
                            s1 = fmaf(zv, wpS[d*192 + g3*64 + jj + 1], s1);
                        }
                        xw0[g3] = s0; xw1[g3] = s1;
                    }
                }
                float bn0 = gru ? bspS[3*64 + jj]     : bnnS[jj];
                float bn1 = gru ? bspS[3*64 + jj + 1] : bnnS[jj + 1];
                float aR0 = acc[0][mi][ni][hh*2+0], aR1 = acc[0][mi][ni][hh*2+1];
                float aZ0 = acc[1][mi][ni][hh*2+0], aZ1 = acc[1][mi][ni][hh*2+1];
                float aN0 = acc[2][mi][ni][hh*2+0], aN1 = acc[2][mi][ni][hh*2+1];

                float2 hp = *(float2*)&g_h[(size_t)(gru*1024 + b)*HP + j];
                float r0 = sigmoidf_(xw0[0] + aR0);
                float r1 = sigmoidf_(xw1[0] + aR1);
                float z0 = sigmoidf_(xw0[1] + aZ0);
                float z1 = sigmoidf_(xw1[1] + aZ1);
                float n0 = tanhf(xw0[2] + r0*(aN0 + bn0));
                float n1 = tanhf(xw1[2] + r1*(aN1 + bn1));
                float h0 = (1.f - z0)*n0 + z0*hp.x;
                float h1 = (1.f - z1)*n1 + z1*hp.y;

                *(float2*)&g_h[(size_t)(gru*1024 + b)*HP + j] = make_float2(h0, h1);

                __half2 hi2 = __floats2half2_rn(h0, h1);
                __half2 lo2 = __floats2half2_rn(h0 - __low2float(hi2), h1 - __high2float(hi2));
                uint32_t sw = swz128((uint32_t)(mrow*128 + (j&63)*2));
                *(__half2*)(g_Ah + a_img(gru, mt, 0, j>>6) + sw) = hi2;
                *(__half2*)(g_Ah + a_img(gru, mt, 1, j>>6) + sw) = lo2;
            }
        }
    }
}

// ----------------------------- qz: mu/std + flows + recon(t-1) ---------------
__global__ __launch_bounds__(128)
void qz_step(int t, const float* __restrict__ eps,
             const float* __restrict__ Wqm, const float* __restrict__ bqm,
             const float* __restrict__ Wqs, const float* __restrict__ bqs,
             const float* __restrict__ fw, const float* __restrict__ fb,
             const float* __restrict__ Wpm, const float* __restrict__ bpm,
             const float* __restrict__ Wps, const float* __restrict__ bps,
             float* __restrict__ out_z, float* __restrict__ out_mu,
             float* __restrict__ out_std, float* __restrict__ out_ld,
             float* __restrict__ out_rm, float* __restrict__ out_rs){
    __shared__ float hq[4][HP];
    __shared__ float hpv[4][HP];
    __shared__ float zp[4][16], zc[4][16], smu[4][16], ssd[4][16];
    int b0 = blockIdx.x*4;
    int tid = threadIdx.x, w = tid>>5, lane = tid&31;

    for (int k=0;k<4;k++){
        int idx = k*128 + tid;
        int r = idx >> 7, q4 = idx & 127;
        ((float4*)hq[r])[q4] = ((const float4*)&g_h[(size_t)(b0+r)*HP])[q4];
        if (t > 0)
            ((float4*)hpv[r])[q4] = ((const float4*)&g_h[(size_t)(1024+b0+r)*HP])[q4];
    }
    if (tid < 64){
        int r = tid >> 4, d = tid & 15;
        zp[r][d] = (t==0) ? 0.f : out_z[((size_t)(b0+r)*T_ + (t-1))*ZD_ + d];
    }
    __syncthreads();

    // mu/std GEMV: 32 outputs, warp-split
    for (int k=0; k<8; k++){
        int o = w + 4*k;
        int oj = o & 15;
        const float* Wrow = ((o < ZD_) ? Wqm : Wqs) + (size_t)oj*(H_+ZD_);
#pragma unroll
        for (int r=0;r<4;r++){
            float acc = 0.f;
            for (int i=lane; i<H_; i+=32) acc = fmaf(hq[r][i], Wrow[i], acc);
            if (lane < ZD_) acc = fmaf(zp[r][lane], Wrow[H_+lane], acc);
#pragma unroll
            for (int off=16; off; off>>=1) acc += __shfl_down_sync(0xFFFFFFFFu, acc, off);
            if (lane == 0){
                size_t oidx = ((size_t)(b0+r)*T_ + t)*ZD_ + oj;
                if (o < ZD_){ float mu = acc + bqm[oj]; smu[r][oj] = mu; out_mu[oidx] = mu; }
                else        { float s = softplusf_(acc + bqs[oj]) + 1e-4f; ssd[r][oj] = s; out_std[oidx] = s; }
            }
        }
    }
    __syncthreads();

    // planar flows: warp w -> batch w
    {
        int r = w, b = b0 + r;
        if (lane < ZD_)
            zc[r][lane] = smu[r][lane] + eps[((size_t)b*T_ + t)*ZD_ + lane]*ssd[r][lane];
        __syncwarp();
        if (lane == 0){
            float ld = 0.f;
#pragma unroll
            for (int k=0;k<L_;k++){
                float dot = 0.f;
                for (int i=0;i<ZD_;i++) dot = fmaf(zc[r][i], fw[k*ZD_+i], dot);
                float hh = tanhf(dot + fb[k]);
                float psiu = 0.f;
                for (int i=0;i<ZD_;i++){
                    zc[r][i] += g_uhat[k*ZD_+i]*hh;
                    psiu = fmaf((1.f - hh*hh)*fw[k*ZD_+i], g_uhat[k*ZD_+i], psiu);
                }
                ld += logf(fabsf(1.f + psiu) + 1e-6f);
            }
            out_ld[b] += ld;
        }
        __syncwarp();
        if (lane < ZD_)
            out_z[((size_t)b*T_ + t)*ZD_ + lane] = zc[r][lane];
    }

    // recon for step t-1 (off critical path)
    if (t > 0){
        for (int o = w; o < 2*XD_; o += 4){
            int d = (o < XD_) ? o : o - XD_;
            const float* Wrow = ((o < XD_) ? Wpm : Wps) + (size_t)d*H_;
#pragma unroll
            for (int r=0;r<4;r++){
                float acc = 0.f;
                for (int i=lane; i<H_; i+=32) acc = fmaf(hpv[r][i], Wrow[i], acc);
#pragma unroll
                for (int off=16; off; off>>=1) acc += __shfl_down_sync(0xFFFFFFFFu, acc, off);
                if (lane == 0){
                    size_t oidx = ((size_t)(b0+r)*T_ + (t-1))*XD_ + d;
                    if (o < XD_) out_rm[oidx] = acc + bpm[d];
                    else         out_rs[oidx] = softplusf_(acc + bps[d]) + 1e-4f;
                }
            }
        }
    }
}

// ----------------------------- final recon (t = T-1) -------------------------
__global__ __launch_bounds__(128)
void recon_last(const float* __restrict__ Wpm, const float* __restrict__ bpm,
                const float* __restrict__ Wps, const float* __restrict__ bps,
                float* __restrict__ out_rm, float* __restrict__ out_rs){
    __shared__ float hpv[4][HP];
    int b0 = blockIdx.x*4;
    int tid = threadIdx.x, w = tid>>5, lane = tid&31;
    for (int k=0;k<4;k++){
        int idx = k*128 + tid;
        int r = idx >> 7, q4 = idx & 127;
        ((float4*)hpv[r])[q4] = ((const float4*)&g_h[(size_t)(1024+b0+r)*HP])[q4];
    }
    __syncthreads();
    for (int o = w; o < 2*XD_; o += 4){
        int d = (o < XD_) ? o : o - XD_;
        const float* Wrow = ((o < XD_) ? Wpm : Wps) + (size_t)d*H_;
#pragma unroll
        for (int r=0;r<4;r++){
            float acc = 0.f;
            for (int i=lane; i<H_; i+=32) acc = fmaf(hpv[r][i], Wrow[i], acc);
#pragma unroll
            for (int off=16; off; off>>=1) acc += __shfl_down_sync(0xFFFFFFFFu, acc, off);
            if (lane == 0){
                size_t oidx = ((size_t)(b0+r)*T_ + (T_-1))*XD_ + d;
                if (o < XD_) out_rm[oidx] = acc + bpm[d];
                else         out_rs[oidx] = softplusf_(acc + bps[d]) + 1e-4f;
            }
        }
    }
}

// ----------------------------- launcher --------------------------------------
extern "C" void kernel_launch(void* const* d_in, const int* in_sizes, int n_in,
                              void* d_out, int out_size){
    const float* x     = (const float*)d_in[0];
    const float* eps   = (const float*)d_in[1];
    const float* Wih_q = (const float*)d_in[2];
    const float* Whh_q = (const float*)d_in[3];
    const float* bih_q = (const float*)d_in[4];
    const float* bhh_q = (const float*)d_in[5];
    const float* Wqm   = (const float*)d_in[6];
    const float* bqm   = (const float*)d_in[7];
    const float* Wqs   = (const float*)d_in[8];
    const float* bqs   = (const float*)d_in[9];
    const float* Wih_p = (const float*)d_in[10];
    const float* Whh_p = (const float*)d_in[11];
    const float* bih_p = (const float*)d_in[12];
    const float* bhh_p = (const float*)d_in[13];
    const float* Wpm   = (const float*)d_in[14];
    const float* bpm   = (const float*)d_in[15];
    const float* Wps   = (const float*)d_in[16];
    const float* bps   = (const float*)d_in[17];
    const float* fu    = (const float*)d_in[18];
    const float* fw    = (const float*)d_in[19];
    const float* fb    = (const float*)d_in[20];

    float* out = (float*)d_out;
    float* out_rm  = out;
    float* out_rs  = out_rm  + (size_t)B_*T_*XD_;
    float* out_z   = out_rs  + (size_t)B_*T_*XD_;
    float* out_mu  = out_z   + (size_t)B_*T_*ZD_;
    float* out_std = out_mu  + (size_t)B_*T_*ZD_;
    float* out_ld  = out_std + (size_t)B_*T_*ZD_;

    cudaFuncSetAttribute(gru_step, cudaFuncAttributeMaxDynamicSharedMemorySize, SMEM_GRU);
    cudaFuncSetAttribute(gx_gemm,  cudaFuncAttributeMaxDynamicSharedMemorySize, SMEM_GX);

    // 4 setup launches (ncu -s 5 lands on the first gru_step)
    init_kernel<<<1024,256>>>(out_ld, fu, fw);                                  // 1
    stage_whh<<<(2*G3H*H_+255)/256,256>>>(Whh_q, Whh_p);                        // 2
    stage_x_wih<<<(B_*T_*XD_ + G3H*XD_ + 255)/256,256>>>(x, Wih_q);             // 3
    gx_gemm<<<dim3(GXNT, GXMT),256,SMEM_GX>>>(bih_q, bhh_q);                    // 4

    dim3 gru_grid(NT_G, MT_G);   // 8 x 16 = 128 CTAs
    for (int t=0; t<T_; t++){
        gru_step<<<gru_grid,256,SMEM_GRU>>>(0, t, out_z, Wih_p, bih_p, bhh_p, bhh_q);
        qz_step<<<B_/4,128>>>(t, eps, Wqm, bqm, Wqs, bqs, fw, fb,
                              Wpm, bpm, Wps, bps,
                              out_z, out_mu, out_std, out_ld, out_rm, out_rs);
        gru_step<<<gru_grid,256,SMEM_GRU>>>(1, t, out_z, Wih_p, bih_p, bhh_p, bhh_q);
    }
    recon_last<<<B_/4,128>>>(Wpm, bpm, Wps, bps, out_rm, out_rs);
}

// round 8
// speedup vs baseline: 1.7250x; 1.1839x over previous
#include <cuda_runtime.h>
#include <cuda_fp16.h>
#include <math.h>
#include <stdint.h>

#define B_   1024
#define T_   100
#define XD_  38
#define H_   500
#define ZD_  16
#define L_   3
#define G3H  1500
#define HP   512          // padded hidden
#define NG   1536         // 3*512 padded gate dim (Gx columns)
#define MT_G 16           // gru M tiles (64 batch rows each)
#define NT_G 8            // gru N tiles (64 hidden each)
#define CH_  8            // K chunks of 64
#define AIMG 8192         // gru A image: 64 rows x 128B
#define BIMG 8192         // B image: 64 rows x 128B
#define GXMT 800          // (B*T)/128
#define GXNT 24           // 1536/64
#define NBZ  8            // batches per qz block
#define SMEM_GRU 100608
#define SMEM_GX  41984

// ----------------------------- device scratch --------------------------------
__device__ __align__(1024) float   g_h[(size_t)2*B_*HP];            // rows 0..1023 hq, 1024.. hp
__device__ __align__(1024) uint8_t g_Ah[(size_t)2*MT_G*2*CH_*AIMG]; // [gru][mt][split][ch]
__device__ __align__(1024) uint8_t g_Bw[(size_t)2*NT_G*3*CH_*BIMG]; // [gru][nt][gate][ch]
__device__ __align__(1024) uint8_t g_Ax[(size_t)GXMT*2*16384];      // [mt][split]
__device__ __align__(1024) uint8_t g_Bx[(size_t)GXNT*BIMG];         // [nt]
__device__ __align__(1024) __half  g_Gx[(size_t)B_*T_*NG];          // 315 MB
__device__ float g_uhat[L_*ZD_];

// ----------------------------- helpers ---------------------------------------
__device__ __forceinline__ float sigmoidf_(float x){ return 1.0f/(1.0f+expf(-x)); }
__device__ __forceinline__ float softplusf_(float x){ return (x>20.0f)? x : log1pf(expf(x)); }
__device__ __forceinline__ uint32_t swz128(uint32_t off){ return off ^ ((off>>3)&0x70); }

__device__ __forceinline__ size_t a_img(int gru,int mt,int split,int ch){
    return ((((size_t)gru*MT_G + mt)*2 + split)*CH_ + ch)*AIMG;
}
__device__ __forceinline__ size_t b_img(int gru,int nt,int gate,int ch){
    return ((((size_t)gru*NT_G + nt)*3 + gate)*CH_ + ch)*BIMG;
}
__device__ __forceinline__ uint32_t smem_u32(const void* p){
    uint32_t a;
    asm("{ .reg .u64 t; cvta.to.shared.u64 t, %1; cvt.u32.u64 %0, t; }" : "=r"(a) : "l"(p));
    return a;
}
__device__ __forceinline__ void cp_async16(uint32_t dst, const void* src){
    asm volatile("cp.async.cg.shared.global [%0], [%1], 16;" :: "r"(dst), "l"(src));
}
__device__ __forceinline__ void cp_commit(){ asm volatile("cp.async.commit_group;" ::: "memory"); }
template<int N>
__device__ __forceinline__ void cp_wait(){ asm volatile("cp.async.wait_group %0;" :: "n"(N) : "memory"); }
__device__ __forceinline__ void ldsm_x4(uint32_t& r0, uint32_t& r1, uint32_t& r2, uint32_t& r3, uint32_t addr){
    asm volatile("ldmatrix.sync.aligned.m8n8.x4.shared.b16 {%0,%1,%2,%3}, [%4];"
                 : "=r"(r0), "=r"(r1), "=r"(r2), "=r"(r3) : "r"(addr));
}
__device__ __forceinline__ void mma_fp16(float* c, const uint32_t* a, const uint32_t* b){
    asm volatile("mma.sync.aligned.m16n8k16.row.col.f32.f16.f16.f32 "
                 "{%0,%1,%2,%3}, {%4,%5,%6,%7}, {%8,%9}, {%0,%1,%2,%3};"
                 : "+f"(c[0]), "+f"(c[1]), "+f"(c[2]), "+f"(c[3])
                 : "r"(a[0]), "r"(a[1]), "r"(a[2]), "r"(a[3]), "r"(b[0]), "r"(b[1]));
}

// ----------------------------- setup launch 1: init --------------------------
__global__ void init_kernel(float* __restrict__ out_ld,
                            const float* __restrict__ fu, const float* __restrict__ fw){
    size_t i = (size_t)blockIdx.x*blockDim.x + threadIdx.x;
    size_t stride = (size_t)gridDim.x*blockDim.x;
    float4* h4 = (float4*)g_h;
    for (size_t k=i; k<sizeof(g_h)/16;  k+=stride) h4[k] = make_float4(0,0,0,0);
    uint4* p;
    p = (uint4*)g_Ah; for (size_t k=i; k<sizeof(g_Ah)/16; k+=stride) p[k] = make_uint4(0,0,0,0);
    p = (uint4*)g_Bw; for (size_t k=i; k<sizeof(g_Bw)/16; k+=stride) p[k] = make_uint4(0,0,0,0);
    p = (uint4*)g_Ax; for (size_t k=i; k<sizeof(g_Ax)/16; k+=stride) p[k] = make_uint4(0,0,0,0);
    p = (uint4*)g_Bx; for (size_t k=i; k<sizeof(g_Bx)/16; k+=stride) p[k] = make_uint4(0,0,0,0);
    for (size_t k=i; k<B_; k+=stride) out_ld[k]=0.f;
    if (i < L_){
        int k = (int)i;
        float wu=0.f, ww=0.f;
        for (int j=0;j<ZD_;j++){ wu += fw[k*ZD_+j]*fu[k*ZD_+j]; ww += fw[k*ZD_+j]*fw[k*ZD_+j]; }
        float m = -1.0f + softplusf_(wu);
        float scale = (m - wu)/(ww + 1e-6f);
        for (int j=0;j<ZD_;j++) g_uhat[k*ZD_+j] = fu[k*ZD_+j] + scale*fw[k*ZD_+j];
    }
}

// ----------------------------- setup launch 2: stage both Whh ----------------
__global__ void stage_whh(const float* __restrict__ Wq, const float* __restrict__ Wp){
    int idx = blockIdx.x*blockDim.x + threadIdx.x;
    if (idx >= 2*G3H*H_) return;
    int gru = idx / (G3H*H_);
    int rem = idx - gru*(G3H*H_);
    int n = rem / H_, k = rem - n*H_;
    float v = (gru ? Wp : Wq)[n*H_ + k];
    int gate = n / 500, j = n - gate*500;
    int nt = j>>6, r = j&63, ch = k>>6, c = k&63;
    *(__half*)(g_Bw + b_img(gru,nt,gate,ch) + swz128((uint32_t)(r*128 + c*2))) = __float2half_rn(v);
}

// ----------------------------- setup launch 3: stage x (split) + Wih_q -------
__global__ void stage_x_wih(const float* __restrict__ x, const float* __restrict__ Wih_q){
    int idx = blockIdx.x*blockDim.x + threadIdx.x;
    const int NX = B_*T_*XD_;
    if (idx < NX){
        int m = idx / XD_, d = idx - m*XD_;          // m = b*T + t
        float v = x[idx];
        int mt = m>>7, r = m&127;
        uint32_t sw = swz128((uint32_t)(r*128 + d*2));
        __half hi = __float2half_rn(v);
        __half lo = __float2half_rn(v - __half2float(hi));
        *(__half*)(g_Ax + (size_t)(mt*2+0)*16384 + sw) = hi;
        *(__half*)(g_Ax + (size_t)(mt*2+1)*16384 + sw) = lo;
    } else if (idx < NX + G3H*XD_){
        int e = idx - NX;
        int n = e / XD_, d = e - n*XD_;
        int gate = n / 500, j = n - gate*500;
        int ni = gate*512 + j;
        int nt = ni>>6, r = ni&63;
        *(__half*)(g_Bx + (size_t)nt*BIMG + swz128((uint32_t)(r*128 + d*2))) =
            __float2half_rn(Wih_q[n*XD_ + d]);
    }
}

// ----------------------------- setup launch 4: Gx = x @ Wih_q^T + bias -------
__global__ __launch_bounds__(256)
void gx_gemm(const float* __restrict__ bih, const float* __restrict__ bhh){
    extern __shared__ uint8_t smem_raw[];
    uint8_t* tiles = (uint8_t*)(((uintptr_t)smem_raw + 1023) & ~(uintptr_t)1023);
    uint32_t sbase = smem_u32(tiles);
    int tid = threadIdx.x, wid = tid>>5, lane = tid&31;
    int nt = blockIdx.x, mt = blockIdx.y;
    int wm = wid & 1, wn = wid >> 1;

    {
        const uint8_t* sa0 = g_Ax + (size_t)(mt*2+0)*16384;
        const uint8_t* sa1 = g_Ax + (size_t)(mt*2+1)*16384;
        const uint8_t* sb  = g_Bx + (size_t)nt*BIMG;
#pragma unroll
        for (int r=0;r<10;r++){
            int idx = r*256 + tid;
            if (idx < 1024)      cp_async16(sbase + idx*16, sa0 + idx*16);
            else if (idx < 2048) cp_async16(sbase + 16384 + (idx-1024)*16, sa1 + (idx-1024)*16);
            else                 cp_async16(sbase + 32768 + (idx-2048)*16, sb + (idx-2048)*16);
        }
    }
    cp_commit(); cp_wait<0>(); __syncthreads();

    float acc[4][2][4];
#pragma unroll
    for (int i=0;i<4;i++)
#pragma unroll
        for (int j=0;j<2;j++)
#pragma unroll
            for (int c=0;c<4;c++) acc[i][j][c]=0.f;

    int g = lane >> 3, l = lane & 7;
    int a_row = wm*64 + (g&1)*8 + l;
    int a_kb  = (g>>1)*16;
    int b_row = wn*16 + (g>>1)*8 + l;
    int b_kb  = (g&1)*16;

#pragma unroll
    for (int s=0; s<4; s++){
        uint32_t Ah[4][4], Al[4][4], Bf[2][2];
        uint32_t a_off = swz128((uint32_t)(a_row*128 + s*32 + a_kb));
        uint32_t b_off = swz128((uint32_t)(b_row*128 + s*32 + b_kb));
#pragma unroll
        for (int mi=0; mi<4; mi++){
            uint32_t ao = a_off + mi*2048;
            ldsm_x4(Ah[mi][0],Ah[mi][1],Ah[mi][2],Ah[mi][3], sbase + ao);
            ldsm_x4(Al[mi][0],Al[mi][1],Al[mi][2],Al[mi][3], sbase + 16384 + ao);
        }
        {
            uint32_t r0,r1,r2,r3;
            ldsm_x4(r0,r1,r2,r3, sbase + 32768 + b_off);
            Bf[0][0]=r0; Bf[0][1]=r1; Bf[1][0]=r2; Bf[1][1]=r3;
        }
#pragma unroll
        for (int mi=0; mi<4; mi++)
#pragma unroll
            for (int ni=0; ni<2; ni++){
                mma_fp16(acc[mi][ni], Ah[mi], Bf[ni]);
                mma_fp16(acc[mi][ni], Al[mi], Bf[ni]);
            }
    }

    int rr = lane>>2, cc = (lane&3)*2;
#pragma unroll
    for (int mi=0; mi<4; mi++){
#pragma unroll
        for (int ni=0; ni<2; ni++){
#pragma unroll
            for (int hh=0; hh<2; hh++){
                int m = mt*128 + wm*64 + mi*16 + hh*8 + rr;
                int n = nt*64 + wn*16 + ni*8 + cc;
                int gate = n>>9, j = n&511;
                float v0 = acc[mi][ni][hh*2+0];
                float v1 = acc[mi][ni][hh*2+1];
                if (j+1 < 500){
                    float b0 = bih[gate*500+j]   + (gate<2 ? bhh[gate*500+j]   : 0.f);
                    float b1 = bih[gate*500+j+1] + (gate<2 ? bhh[gate*500+j+1] : 0.f);
                    v0 += b0; v1 += b1;
                }
                *(__half2*)&g_Gx[(size_t)m*NG + n] = __floats2half2_rn(v0, v1);
            }
        }
    }
}

// ----------------------------- combined GRU step: p(tp) and q(tq) ------------
// CTAs with blockIdx.y < 16 run the p-GRU at time tp (if do_p);
// CTAs with blockIdx.y >= 16 run the q-GRU at time tq (if do_q).
__global__ __launch_bounds__(256)
void gru_pq(int tp, int do_p, int tq, int do_q,
            const float* __restrict__ out_z,
            const float* __restrict__ Wihp,
            const float* __restrict__ bihp, const float* __restrict__ bhhp,
            const float* __restrict__ bhhq){
    int role = blockIdx.y >> 4;          // 0 -> p, 1 -> q
    int gru  = role ? 0 : 1;
    if (gru == 1 && !do_p) return;
    if (gru == 0 && !do_q) return;
    int t = gru ? tp : tq;

    extern __shared__ uint8_t smem_raw[];
    uint8_t* tiles = (uint8_t*)(((uintptr_t)smem_raw + 1023) & ~(uintptr_t)1023);
    uint32_t sbase = smem_u32(tiles);
    float* zzS  = (float*)(tiles + 81920);            // p: [64][17]
    float* wpS  = (float*)(tiles + 86272);            // p: [16][192]
    float* bspS = (float*)(tiles + 98560);            // p: [4][64]
    float* bnnS = (float*)(tiles + 81920);            // q: [64]

    int tid = threadIdx.x, wid = tid>>5, lane = tid&31;
    int nt = blockIdx.x, mt = blockIdx.y & 15;
    int wm = wid & 1, wn = wid >> 1;

    auto copy_chunk = [&](int ch, int buf){
        const uint8_t* srcs[5] = {
            g_Ah + a_img(gru,mt,0,ch), g_Ah + a_img(gru,mt,1,ch),
            g_Bw + b_img(gru,nt,0,ch), g_Bw + b_img(gru,nt,1,ch), g_Bw + b_img(gru,nt,2,ch)
        };
        uint32_t dbase = sbase + buf*40960;
#pragma unroll
        for (int r=0;r<10;r++){
            int idx = r*256 + tid;
            int img = idx >> 9;
            int off = (idx & 511)*16;
            cp_async16(dbase + img*8192 + off, srcs[img] + off);
        }
    };

    copy_chunk(0,0); cp_commit();

    if (!gru){
        if (tid < 64){
            int j = nt*64 + tid;
            bnnS[tid] = (j < 500) ? bhhq[1000 + j] : 0.f;
        }
    } else {
        for (int idx = tid; idx < 64*ZD_; idx += 256){
            int r = idx >> 4, d = idx & 15;
            int b = mt*64 + r;
            zzS[r*17 + d] = out_z[((size_t)b*T_ + t)*ZD_ + d];
        }
        for (int idx = tid; idx < ZD_*192; idx += 256){
            int d = idx & 15, col = idx >> 4;
            int gg = col >> 6, jj = col & 63;
            int j = nt*64 + jj;
            wpS[d*192 + col] = (j < 500) ? Wihp[((size_t)(gg*500 + j))*ZD_ + d] : 0.f;
        }
        if (tid < 256){
            int q4 = tid >> 6, jj = tid & 63;
            int j = nt*64 + jj;
            float v = 0.f;
            if (j < 500){
                if (q4 == 0) v = bihp[j]       + bhhp[j];
                else if (q4 == 1) v = bihp[500+j]  + bhhp[500+j];
                else if (q4 == 2) v = bihp[1000+j];
                else v = bhhp[1000+j];
            }
            bspS[q4*64 + jj] = v;
        }
    }
    __syncthreads();

    float acc[3][2][2][4];
#pragma unroll
    for (int a=0;a<3;a++)
#pragma unroll
        for (int i=0;i<2;i++)
#pragma unroll
            for (int j=0;j<2;j++)
#pragma unroll
                for (int c=0;c<4;c++) acc[a][i][j][c]=0.f;

    int g = lane >> 3, l = lane & 7;
    int a_row = wm*32 + (g&1)*8 + l;
    int a_kb  = (g>>1)*16;
    int b_row = wn*16 + (g>>1)*8 + l;
    int b_kb  = (g&1)*16;

    for (int ch=0; ch<CH_; ch++){
        if (ch+1 < CH_){ copy_chunk(ch+1,(ch+1)&1); cp_commit(); cp_wait<1>(); }
        else cp_wait<0>();
        __syncthreads();

        uint32_t Ahi_b = sbase + (ch&1)*40960;
        uint32_t Alo_b = Ahi_b + 8192;
        uint32_t Bb    = Ahi_b + 16384;

#pragma unroll
        for (int s=0; s<4; s++){
            uint32_t Ah[2][4], Al[2][4], Bf[3][2][2];
            uint32_t a_off = swz128((uint32_t)(a_row*128 + s*32 + a_kb));
            uint32_t b_off = swz128((uint32_t)(b_row*128 + s*32 + b_kb));
#pragma unroll
            for (int mi=0; mi<2; mi++){
                uint32_t ao = a_off + mi*2048;
                ldsm_x4(Ah[mi][0],Ah[mi][1],Ah[mi][2],Ah[mi][3], Ahi_b + ao);
                ldsm_x4(Al[mi][0],Al[mi][1],Al[mi][2],Al[mi][3], Alo_b + ao);
            }
#pragma unroll
            for (int g3=0; g3<3; g3++){
                uint32_t r0,r1,r2,r3;
                ldsm_x4(r0,r1,r2,r3, Bb + g3*8192 + b_off);
                Bf[g3][0][0]=r0; Bf[g3][0][1]=r1; Bf[g3][1][0]=r2; Bf[g3][1][1]=r3;
            }
#pragma unroll
            for (int g3=0; g3<3; g3++)
#pragma unroll
                for (int mi=0; mi<2; mi++)
#pragma unroll
                    for (int ni=0; ni<2; ni++){
                        mma_fp16(acc[g3][mi][ni], Ah[mi], Bf[g3][ni]);
                        mma_fp16(acc[g3][mi][ni], Al[mi], Bf[g3][ni]);
                    }
        }
        __syncthreads();
    }

    // -------- epilogue: GRU combine in registers --------
    int rr = lane>>2, cc = (lane&3)*2;
#pragma unroll
    for (int mi=0; mi<2; mi++){
#pragma unroll
        for (int hh=0; hh<2; hh++){
            int mrow = wm*32 + mi*16 + hh*8 + rr;
            int b = mt*64 + mrow;
            float zr[ZD_];
            if (gru){
#pragma unroll
                for (int d=0; d<ZD_; d++) zr[d] = zzS[mrow*17 + d];
            }
#pragma unroll
            for (int ni=0; ni<2; ni++){
                int jj = wn*16 + ni*8 + cc;
                int j = nt*64 + jj;
                if (j >= 500) continue;
                float xw0[3], xw1[3];
                if (!gru){
                    size_t base = ((size_t)b*T_ + t)*NG + j;
#pragma unroll
                    for (int g3=0; g3<3; g3++){
                        __half2 hv = *(const __half2*)&g_Gx[base + g3*512];
                        xw0[g3] = __low2float(hv);
                        xw1[g3] = __high2float(hv);
                    }
                } else {
#pragma unroll
                    for (int g3=0; g3<3; g3++){
                        float s0 = bspS[g3*64 + jj];
                        float s1 = bspS[g3*64 + jj + 1];
#pragma unroll
                        for (int d=0; d<ZD_; d++){
                            float zv = zr[d];
                            s0 = fmaf(zv, wpS[d*192 + g3*64 + jj],     s0);
                            s1 = fmaf(zv, wpS[d*192 + g3*64 + jj + 1], s1);
                        }
                        xw0[g3] = s0; xw1[g3] = s1;
                    }
                }
                float bn0 = gru ? bspS[3*64 + jj]     : bnnS[jj];
                float bn1 = gru ? bspS[3*64 + jj + 1] : bnnS[jj + 1];
                float aR0 = acc[0][mi][ni][hh*2+0], aR1 = acc[0][mi][ni][hh*2+1];
                float aZ0 = acc[1][mi][ni][hh*2+0], aZ1 = acc[1][mi][ni][hh*2+1];
                float aN0 = acc[2][mi][ni][hh*2+0], aN1 = acc[2][mi][ni][hh*2+1];

                float2 hp = *(float2*)&g_h[(size_t)(gru*1024 + b)*HP + j];
                float r0 = sigmoidf_(xw0[0] + aR0);
                float r1 = sigmoidf_(xw1[0] + aR1);
                float z0 = sigmoidf_(xw0[1] + aZ0);
                float z1 = sigmoidf_(xw1[1] + aZ1);
                float n0 = tanhf(xw0[2] + r0*(aN0 + bn0));
                float n1 = tanhf(xw1[2] + r1*(aN1 + bn1));
                float h0 = (1.f - z0)*n0 + z0*hp.x;
                float h1 = (1.f - z1)*n1 + z1*hp.y;

                *(float2*)&g_h[(size_t)(gru*1024 + b)*HP + j] = make_float2(h0, h1);

                __half2 hi2 = __floats2half2_rn(h0, h1);
                __half2 lo2 = __floats2half2_rn(h0 - __low2float(hi2), h1 - __high2float(hi2));
                uint32_t sw = swz128((uint32_t)(mrow*128 + (j&63)*2));
                *(__half2*)(g_Ah + a_img(gru, mt, 0, j>>6) + sw) = hi2;
                *(__half2*)(g_Ah + a_img(gru, mt, 1, j>>6) + sw) = lo2;
            }
        }
    }
}

// ----------------------------- qz: mu/std + flows + recon(t-1) ---------------
// 8 batches per block, 256 threads, 128 blocks.
__global__ __launch_bounds__(256)
void qz_step(int t, const float* __restrict__ eps,
             const float* __restrict__ Wqm, const float* __restrict__ bqm,
             const float* __restrict__ Wqs, const float* __restrict__ bqs,
             const float* __restrict__ fw, const float* __restrict__ fb,
             const float* __restrict__ Wpm, const float* __restrict__ bpm,
             const float* __restrict__ Wps, const float* __restrict__ bps,
             float* __restrict__ out_z, float* __restrict__ out_mu,
             float* __restrict__ out_std, float* __restrict__ out_ld,
             float* __restrict__ out_rm, float* __restrict__ out_rs){
    __shared__ float hq[NBZ][HP];
    __shared__ float hpv[NBZ][HP];
    __shared__ float zp[NBZ][16], zc[NBZ][16], smu[NBZ][16], ssd[NBZ][16];
    int b0 = blockIdx.x*NBZ;
    int tid = threadIdx.x, w = tid>>5, lane = tid&31;

    for (int k=0;k<4;k++){
        int idx = k*256 + tid;          // 0..1023 -> 8 rows x 128 float4
        int r = idx >> 7, q4 = idx & 127;
        ((float4*)hq[r])[q4] = ((const float4*)&g_h[(size_t)(b0+r)*HP])[q4];
        if (t > 0)
            ((float4*)hpv[r])[q4] = ((const float4*)&g_h[(size_t)(1024+b0+r)*HP])[q4];
    }
    if (tid < NBZ*16){
        int r = tid >> 4, d = tid & 15;
        zp[r][d] = (t==0) ? 0.f : out_z[((size_t)(b0+r)*T_ + (t-1))*ZD_ + d];
    }
    __syncthreads();

    // mu/std GEMV: 32 outputs, 8 warps x 4 outputs
    for (int k=0; k<4; k++){
        int o = w + 8*k;
        int oj = o & 15;
        const float* Wrow = ((o < ZD_) ? Wqm : Wqs) + (size_t)oj*(H_+ZD_);
#pragma unroll
        for (int r=0;r<NBZ;r++){
            float acc = 0.f;
            for (int i=lane; i<H_; i+=32) acc = fmaf(hq[r][i], Wrow[i], acc);
            if (lane < ZD_) acc = fmaf(zp[r][lane], Wrow[H_+lane], acc);
#pragma unroll
            for (int off=16; off; off>>=1) acc += __shfl_down_sync(0xFFFFFFFFu, acc, off);
            if (lane == 0){
                size_t oidx = ((size_t)(b0+r)*T_ + t)*ZD_ + oj;
                if (o < ZD_){ float mu = acc + bqm[oj]; smu[r][oj] = mu; out_mu[oidx] = mu; }
                else        { float s = softplusf_(acc + bqs[oj]) + 1e-4f; ssd[r][oj] = s; out_std[oidx] = s; }
            }
        }
    }
    __syncthreads();

    // planar flows: warp w -> batch w
    {
        int r = w, b = b0 + r;
        if (lane < ZD_)
            zc[r][lane] = smu[r][lane] + eps[((size_t)b*T_ + t)*ZD_ + lane]*ssd[r][lane];
        __syncwarp();
        if (lane == 0){
            float ld = 0.f;
#pragma unroll
            for (int k=0;k<L_;k++){
                float dot = 0.f;
                for (int i=0;i<ZD_;i++) dot = fmaf(zc[r][i], fw[k*ZD_+i], dot);
                float hh = tanhf(dot + fb[k]);
                float psiu = 0.f;
                for (int i=0;i<ZD_;i++){
                    zc[r][i] += g_uhat[k*ZD_+i]*hh;
                    psiu = fmaf((1.f - hh*hh)*fw[k*ZD_+i], g_uhat[k*ZD_+i], psiu);
                }
                ld += logf(fabsf(1.f + psiu) + 1e-6f);
            }
            out_ld[b] += ld;
        }
        __syncwarp();
        if (lane < ZD_)
            out_z[((size_t)b*T_ + t)*ZD_ + lane] = zc[r][lane];
    }

    // recon for step t-1 (off critical path)
    if (t > 0){
        for (int o = w; o < 2*XD_; o += 8){
            int d = (o < XD_) ? o : o - XD_;
            const float* Wrow = ((o < XD_) ? Wpm : Wps) + (size_t)d*H_;
#pragma unroll
            for (int r=0;r<NBZ;r++){
                float acc = 0.f;
                for (int i=lane; i<H_; i+=32) acc = fmaf(hpv[r][i], Wrow[i], acc);
#pragma unroll
                for (int off=16; off; off>>=1) acc += __shfl_down_sync(0xFFFFFFFFu, acc, off);
                if (lane == 0){
                    size_t oidx = ((size_t)(b0+r)*T_ + (t-1))*XD_ + d;
                    if (o < XD_) out_rm[oidx] = acc + bpm[d];
                    else         out_rs[oidx] = softplusf_(acc + bps[d]) + 1e-4f;
                }
            }
        }
    }
}

// ----------------------------- final recon (t = T-1) -------------------------
__global__ __launch_bounds__(256)
void recon_last(const float* __restrict__ Wpm, const float* __restrict__ bpm,
                const float* __restrict__ Wps, const float* __restrict__ bps,
                float* __restrict__ out_rm, float* __restrict__ out_rs){
    __shared__ float hpv[NBZ][HP];
    int b0 = blockIdx.x*NBZ;
    int tid = threadIdx.x, w = tid>>5, lane = tid&31;
    for (int k=0;k<4;k++){
        int idx = k*256 + tid;
        int r = idx >> 7, q4 = idx & 127;
        ((float4*)hpv[r])[q4] = ((const float4*)&g_h[(size_t)(1024+b0+r)*HP])[q4];
    }
    __syncthreads();
    for (int o = w; o < 2*XD_; o += 8){
        int d = (o < XD_) ? o : o - XD_;
        const float* Wrow = ((o < XD_) ? Wpm : Wps) + (size_t)d*H_;
#pragma unroll
        for (int r=0;r<NBZ;r++){
            float acc = 0.f;
            for (int i=lane; i<H_; i+=32) acc = fmaf(hpv[r][i], Wrow[i], acc);
#pragma unroll
            for (int off=16; off; off>>=1) acc += __shfl_down_sync(0xFFFFFFFFu, acc, off);
            if (lane == 0){
                size_t oidx = ((size_t)(b0+r)*T_ + (T_-1))*XD_ + d;
                if (o < XD_) out_rm[oidx] = acc + bpm[d];
                else         out_rs[oidx] = softplusf_(acc + bps[d]) + 1e-4f;
            }
        }
    }
}

// ----------------------------- launcher --------------------------------------
extern "C" void kernel_launch(void* const* d_in, const int* in_sizes, int n_in,
                              void* d_out, int out_size){
    const float* x     = (const float*)d_in[0];
    const float* eps   = (const float*)d_in[1];
    const float* Wih_q = (const float*)d_in[2];
    const float* Whh_q = (const float*)d_in[3];
    const float* bih_q = (const float*)d_in[4];
    const float* bhh_q = (const float*)d_in[5];
    const float* Wqm   = (const float*)d_in[6];
    const float* bqm   = (const float*)d_in[7];
    const float* Wqs   = (const float*)d_in[8];
    const float* bqs   = (const float*)d_in[9];
    const float* Wih_p = (const float*)d_in[10];
    const float* Whh_p = (const float*)d_in[11];
    const float* bih_p = (const float*)d_in[12];
    const float* bhh_p = (const float*)d_in[13];
    const float* Wpm   = (const float*)d_in[14];
    const float* bpm   = (const float*)d_in[15];
    const float* Wps   = (const float*)d_in[16];
    const float* bps   = (const float*)d_in[17];
    const float* fu    = (const float*)d_in[18];
    const float* fw    = (const float*)d_in[19];
    const float* fb    = (const float*)d_in[20];

    float* out = (float*)d_out;
    float* out_rm  = out;
    float* out_rs  = out_rm  + (size_t)B_*T_*XD_;
    float* out_z   = out_rs  + (size_t)B_*T_*XD_;
    float* out_mu  = out_z   + (size_t)B_*T_*ZD_;
    float* out_std = out_mu  + (size_t)B_*T_*ZD_;
    float* out_ld  = out_std + (size_t)B_*T_*ZD_;

    cudaFuncSetAttribute(gru_pq,  cudaFuncAttributeMaxDynamicSharedMemorySize, SMEM_GRU);
    cudaFuncSetAttribute(gx_gemm, cudaFuncAttributeMaxDynamicSharedMemorySize, SMEM_GX);

    // 4 setup launches + prologue; ncu -s 5 lands on the first gru_pq
    init_kernel<<<1024,256>>>(out_ld, fu, fw);                                  // 1
    stage_whh<<<(2*G3H*H_+255)/256,256>>>(Whh_q, Whh_p);                        // 2
    stage_x_wih<<<(B_*T_*XD_ + G3H*XD_ + 255)/256,256>>>(x, Wih_q);             // 3
    gx_gemm<<<dim3(GXNT, GXMT),256,SMEM_GX>>>(bih_q, bhh_q);                    // 4

    dim3 pq_grid(NT_G, 32);   // 8 x 32 = 256 CTAs (p-half + q-half)

    // prologue: q(0) only
    gru_pq<<<pq_grid,256,SMEM_GRU>>>(0, 0, 0, 1, out_z, Wih_p, bih_p, bhh_p, bhh_q);

    for (int t=0; t<T_; t++){
        // mu/std + flows + z(t) + recon(t-1)
        qz_step<<<B_/NBZ,256>>>(t, eps, Wqm, bqm, Wqs, bqs, fw, fb,
                                Wpm, bpm, Wps, bps,
                                out_z, out_mu, out_std, out_ld, out_rm, out_rs);
        // p(t) and q(t+1) in ONE launch (independent of each other)
        gru_pq<<<pq_grid,256,SMEM_GRU>>>(t, 1, t+1, (t+1 < T_) ? 1 : 0,
                                         out_z, Wih_p, bih_p, bhh_p, bhh_q);
    }
    recon_last<<<B_/NBZ,256>>>(Wpm, bpm, Wps, bps, out_rm, out_rs);
}

// round 10
// speedup vs baseline: 2.4102x; 1.3972x over previous
#include <cuda_runtime.h>
#include <cuda_fp16.h>
#include <math.h>
#include <stdint.h>

#define B_   1024
#define T_   100
#define XD_  38
#define H_   500
#define ZD_  16
#define L_   3
#define G3H  1500
#define HP   512
#define NG   1536
#define MT_G 16
#define NT_G 8
#define CH_  8
#define AIMG 8192
#define BIMG 8192
#define GXMT 800
#define GXNT 24
#define RROWS 32
#define SMEM_GRU 100608
#define SMEM_GX  41984
#define SMEM_RC  65536

// ----------------------------- device scratch --------------------------------
__device__ __align__(1024) float   g_h[(size_t)2*B_*HP];
// A-images double-buffered by step parity: [gru][par][mt][split][ch]
__device__ __align__(1024) uint8_t g_Ah[(size_t)2*2*MT_G*2*CH_*AIMG];
__device__ __align__(1024) uint8_t g_Bw[(size_t)2*NT_G*3*CH_*BIMG];
__device__ __align__(1024) uint8_t g_Ax[(size_t)GXMT*2*16384];
__device__ __align__(1024) uint8_t g_Bx[(size_t)GXNT*BIMG];
__device__ __align__(1024) __half  g_Gx[(size_t)B_*T_*NG];
__device__ __align__(1024) float   g_hist[(size_t)B_*T_*HP];      // hp history (fp32)
__device__ float g_part[2][NT_G][B_][32];                          // mu/std partials
__device__ float g_uhat[L_*ZD_];

// ----------------------------- helpers ---------------------------------------
__device__ __forceinline__ float sigmoidf_(float x){ return 1.0f/(1.0f+expf(-x)); }
__device__ __forceinline__ float softplusf_(float x){ return (x>20.0f)? x : log1pf(expf(x)); }
__device__ __forceinline__ uint32_t swz128(uint32_t off){ return off ^ ((off>>3)&0x70); }

__device__ __forceinline__ size_t a_img(int gru,int par,int mt,int split,int ch){
    return (((((size_t)gru*2 + par)*MT_G + mt)*2 + split)*CH_ + ch)*AIMG;
}
__device__ __forceinline__ size_t b_img(int gru,int nt,int gate,int ch){
    return ((((size_t)gru*NT_G + nt)*3 + gate)*CH_ + ch)*BIMG;
}
__device__ __forceinline__ uint32_t smem_u32(const void* p){
    uint32_t a;
    asm("{ .reg .u64 t; cvta.to.shared.u64 t, %1; cvt.u32.u64 %0, t; }" : "=r"(a) : "l"(p));
    return a;
}
__device__ __forceinline__ void cp_async16(uint32_t dst, const void* src){
    asm volatile("cp.async.cg.shared.global [%0], [%1], 16;" :: "r"(dst), "l"(src));
}
__device__ __forceinline__ void cp_commit(){ asm volatile("cp.async.commit_group;" ::: "memory"); }
template<int N>
__device__ __forceinline__ void cp_wait(){ asm volatile("cp.async.wait_group %0;" :: "n"(N) : "memory"); }
__device__ __forceinline__ void ldsm_x4(uint32_t& r0, uint32_t& r1, uint32_t& r2, uint32_t& r3, uint32_t addr){
    asm volatile("ldmatrix.sync.aligned.m8n8.x4.shared.b16 {%0,%1,%2,%3}, [%4];"
                 : "=r"(r0), "=r"(r1), "=r"(r2), "=r"(r3) : "r"(addr));
}
__device__ __forceinline__ void mma_fp16(float* c, const uint32_t* a, const uint32_t* b){
    asm volatile("mma.sync.aligned.m16n8k16.row.col.f32.f16.f16.f32 "
                 "{%0,%1,%2,%3}, {%4,%5,%6,%7}, {%8,%9}, {%0,%1,%2,%3};"
                 : "+f"(c[0]), "+f"(c[1]), "+f"(c[2]), "+f"(c[3])
                 : "r"(a[0]), "r"(a[1]), "r"(a[2]), "r"(a[3]), "r"(b[0]), "r"(b[1]));
}

// ----------------------------- setup launch 1: init --------------------------
__global__ void init_kernel(float* __restrict__ out_ld,
                            const float* __restrict__ fu, const float* __restrict__ fw){
    size_t i = (size_t)blockIdx.x*blockDim.x + threadIdx.x;
    size_t stride = (size_t)gridDim.x*blockDim.x;
    float4* h4 = (float4*)g_h;
    for (size_t k=i; k<sizeof(g_h)/16;  k+=stride) h4[k] = make_float4(0,0,0,0);
    uint4* p;
    p = (uint4*)g_Ah; for (size_t k=i; k<sizeof(g_Ah)/16; k+=stride) p[k] = make_uint4(0,0,0,0);
    p = (uint4*)g_Bw; for (size_t k=i; k<sizeof(g_Bw)/16; k+=stride) p[k] = make_uint4(0,0,0,0);
    p = (uint4*)g_Ax; for (size_t k=i; k<sizeof(g_Ax)/16; k+=stride) p[k] = make_uint4(0,0,0,0);
    p = (uint4*)g_Bx; for (size_t k=i; k<sizeof(g_Bx)/16; k+=stride) p[k] = make_uint4(0,0,0,0);
    for (size_t k=i; k<B_; k+=stride) out_ld[k]=0.f;
    if (i < L_){
        int k = (int)i;
        float wu=0.f, ww=0.f;
        for (int j=0;j<ZD_;j++){ wu += fw[k*ZD_+j]*fu[k*ZD_+j]; ww += fw[k*ZD_+j]*fw[k*ZD_+j]; }
        float m = -1.0f + softplusf_(wu);
        float scale = (m - wu)/(ww + 1e-6f);
        for (int j=0;j<ZD_;j++) g_uhat[k*ZD_+j] = fu[k*ZD_+j] + scale*fw[k*ZD_+j];
    }
}

// ----------------------------- setup launch 2: stage both Whh ----------------
__global__ void stage_whh(const float* __restrict__ Wq, const float* __restrict__ Wp){
    int idx = blockIdx.x*blockDim.x + threadIdx.x;
    if (idx >= 2*G3H*H_) return;
    int gru = idx / (G3H*H_);
    int rem = idx - gru*(G3H*H_);
    int n = rem / H_, k = rem - n*H_;
    float v = (gru ? Wp : Wq)[n*H_ + k];
    int gate = n / 500, j = n - gate*500;
    int nt = j>>6, r = j&63, ch = k>>6, c = k&63;
    *(__half*)(g_Bw + b_img(gru,nt,gate,ch) + swz128((uint32_t)(r*128 + c*2))) = __float2half_rn(v);
}

// ----------------------------- setup launch 3: stage x (split) + Wih_q -------
__global__ void stage_x_wih(const float* __restrict__ x, const float* __restrict__ Wih_q){
    int idx = blockIdx.x*blockDim.x + threadIdx.x;
    const int NX = B_*T_*XD_;
    if (idx < NX){
        int m = idx / XD_, d = idx - m*XD_;
        float v = x[idx];
        int mt = m>>7, r = m&127;
        uint32_t sw = swz128((uint32_t)(r*128 + d*2));
        __half hi = __float2half_rn(v);
        __half lo = __float2half_rn(v - __half2float(hi));
        *(__half*)(g_Ax + (size_t)(mt*2+0)*16384 + sw) = hi;
        *(__half*)(g_Ax + (size_t)(mt*2+1)*16384 + sw) = lo;
    } else if (idx < NX + G3H*XD_){
        int e = idx - NX;
        int n = e / XD_, d = e - n*XD_;
        int gate = n / 500, j = n - gate*500;
        int ni = gate*512 + j;
        int nt = ni>>6, r = ni&63;
        *(__half*)(g_Bx + (size_t)nt*BIMG + swz128((uint32_t)(r*128 + d*2))) =
            __float2half_rn(Wih_q[n*XD_ + d]);
    }
}

// ----------------------------- setup launch 4: Gx = x @ Wih_q^T + bias -------
__global__ __launch_bounds__(256)
void gx_gemm(const float* __restrict__ bih, const float* __restrict__ bhh){
    extern __shared__ uint8_t smem_raw[];
    uint8_t* tiles = (uint8_t*)(((uintptr_t)smem_raw + 1023) & ~(uintptr_t)1023);
    uint32_t sbase = smem_u32(tiles);
    int tid = threadIdx.x, wid = tid>>5, lane = tid&31;
    int nt = blockIdx.x, mt = blockIdx.y;
    int wm = wid & 1, wn = wid >> 1;

    {
        const uint8_t* sa0 = g_Ax + (size_t)(mt*2+0)*16384;
        const uint8_t* sa1 = g_Ax + (size_t)(mt*2+1)*16384;
        const uint8_t* sb  = g_Bx + (size_t)nt*BIMG;
#pragma unroll
        for (int r=0;r<10;r++){
            int idx = r*256 + tid;
            if (idx < 1024)      cp_async16(sbase + idx*16, sa0 + idx*16);
            else if (idx < 2048) cp_async16(sbase + 16384 + (idx-1024)*16, sa1 + (idx-1024)*16);
            else                 cp_async16(sbase + 32768 + (idx-2048)*16, sb + (idx-2048)*16);
        }
    }
    cp_commit(); cp_wait<0>(); __syncthreads();

    float acc[4][2][4];
#pragma unroll
    for (int i=0;i<4;i++)
#pragma unroll
        for (int j=0;j<2;j++)
#pragma unroll
            for (int c=0;c<4;c++) acc[i][j][c]=0.f;

    int g = lane >> 3, l = lane & 7;
    int a_row = wm*64 + (g&1)*8 + l;
    int a_kb  = (g>>1)*16;
    int b_row = wn*16 + (g>>1)*8 + l;
    int b_kb  = (g&1)*16;

#pragma unroll
    for (int s=0; s<4; s++){
        uint32_t Ah[4][4], Al[4][4], Bf[2][2];
        uint32_t a_off = swz128((uint32_t)(a_row*128 + s*32 + a_kb));
        uint32_t b_off = swz128((uint32_t)(b_row*128 + s*32 + b_kb));
#pragma unroll
        for (int mi=0; mi<4; mi++){
            uint32_t ao = a_off + mi*2048;
            ldsm_x4(Ah[mi][0],Ah[mi][1],Ah[mi][2],Ah[mi][3], sbase + ao);
            ldsm_x4(Al[mi][0],Al[mi][1],Al[mi][2],Al[mi][3], sbase + 16384 + ao);
        }
        {
            uint32_t r0,r1,r2,r3;
            ldsm_x4(r0,r1,r2,r3, sbase + 32768 + b_off);
            Bf[0][0]=r0; Bf[0][1]=r1; Bf[1][0]=r2; Bf[1][1]=r3;
        }
#pragma unroll
        for (int mi=0; mi<4; mi++)
#pragma unroll
            for (int ni=0; ni<2; ni++){
                mma_fp16(acc[mi][ni], Ah[mi], Bf[ni]);
                mma_fp16(acc[mi][ni], Al[mi], Bf[ni]);
            }
    }

    int rr = lane>>2, cc = (lane&3)*2;
#pragma unroll
    for (int mi=0; mi<4; mi++){
#pragma unroll
        for (int ni=0; ni<2; ni++){
#pragma unroll
            for (int hh=0; hh<2; hh++){
                int m = mt*128 + wm*64 + mi*16 + hh*8 + rr;
                int n = nt*64 + wn*16 + ni*8 + cc;
                int gate = n>>9, j = n&511;
                float v0 = acc[mi][ni][hh*2+0];
                float v1 = acc[mi][ni][hh*2+1];
                if (j+1 < 500){
                    float b0 = bih[gate*500+j]   + (gate<2 ? bhh[gate*500+j]   : 0.f);
                    float b1 = bih[gate*500+j+1] + (gate<2 ? bhh[gate*500+j+1] : 0.f);
                    v0 += b0; v1 += b1;
                }
                *(__half2*)&g_Gx[(size_t)m*NG + n] = __floats2half2_rn(v0, v1);
            }
        }
    }
}

// ----------------------------- combined step: p(tp) + q(tq) + z(tp) ----------
// A-images are parity double-buffered: step t reads parity (t-1)&1, writes t&1.
__global__ __launch_bounds__(256)
void gru_pq(int tp, int do_p, int tq, int do_q,
            const float* __restrict__ eps,
            const float* __restrict__ Wihp,
            const float* __restrict__ bihp, const float* __restrict__ bhhp,
            const float* __restrict__ bhhq,
            const float* __restrict__ Wqm, const float* __restrict__ bqm,
            const float* __restrict__ Wqs, const float* __restrict__ bqs,
            const float* __restrict__ fw, const float* __restrict__ fb,
            float* __restrict__ out_z, float* __restrict__ out_mu,
            float* __restrict__ out_std, float* __restrict__ out_ld){
    int role = blockIdx.y >> 4;          // 0 -> p, 1 -> q
    int gru  = role ? 0 : 1;
    if (gru == 1 && !do_p) return;
    if (gru == 0 && !do_q) return;
    int t = gru ? tp : tq;
    int par_w = t & 1;
    int par_r = par_w ^ 1;

    extern __shared__ uint8_t smem_raw[];
    uint8_t* tiles = (uint8_t*)(((uintptr_t)smem_raw + 1023) & ~(uintptr_t)1023);
    uint32_t sbase = smem_u32(tiles);
    float* zzS  = (float*)(tiles + 81920);            // p: [64][17]
    float* wpS  = (float*)(tiles + 86272);            // p: [16][192]
    float* bspS = (float*)(tiles + 98560);            // p: [4][64]
    float* bnnS = (float*)(tiles + 81920);            // q: [64]

    int tid = threadIdx.x, wid = tid>>5, lane = tid&31;
    int nt = blockIdx.x, mt = blockIdx.y & 15;
    int wm = wid & 1, wn = wid >> 1;

    auto copy_chunk = [&](int ch, int buf){
        const uint8_t* srcs[5] = {
            g_Ah + a_img(gru,par_r,mt,0,ch), g_Ah + a_img(gru,par_r,mt,1,ch),
            g_Bw + b_img(gru,nt,0,ch), g_Bw + b_img(gru,nt,1,ch), g_Bw + b_img(gru,nt,2,ch)
        };
        uint32_t dbase = sbase + buf*40960;
#pragma unroll
        for (int r=0;r<10;r++){
            int idx = r*256 + tid;
            int img = idx >> 9;
            int off = (idx & 511)*16;
            cp_async16(dbase + img*8192 + off, srcs[img] + off);
        }
    };

    copy_chunk(0,0); cp_commit();

    if (!gru){
        if (tid < 64){
            int j = nt*64 + tid;
            bnnS[tid] = (j < 500) ? bhhq[1000 + j] : 0.f;
        }
    } else {
        // ---------- p prologue: compute z(t) from partials + flows ----------
        float* zpS = (float*)(tiles + 40960);   // [64][16]
        float* WzS = (float*)(tiles + 45056);   // [16][32]
        float* muS = (float*)(tiles + 47104);   // [64][16]
        float* sdS = (float*)(tiles + 51200);   // [64][16]
        for (int idx = tid; idx < 64*16; idx += 256){
            int r = idx >> 4, d = idx & 15;
            zpS[idx] = (t==0) ? 0.f : out_z[((size_t)(mt*64+r)*T_ + (t-1))*ZD_ + d];
        }
        for (int idx = tid; idx < 16*32; idx += 256){
            int d = idx >> 5, o = idx & 31;
            WzS[idx] = (o < 16) ? Wqm[o*(H_+ZD_) + H_ + d]
                                : Wqs[(o-16)*(H_+ZD_) + H_ + d];
        }
        __syncthreads();
        for (int idx = tid; idx < 64*32; idx += 256){
            int b = idx >> 5, o = idx & 31;
            int gb = mt*64 + b;
            float s = 0.f;
#pragma unroll
            for (int q8 = 0; q8 < NT_G; q8++) s += g_part[t&1][q8][gb][o];
#pragma unroll
            for (int d = 0; d < ZD_; d++) s = fmaf(zpS[b*16+d], WzS[d*32+o], s);
            if (o < 16){
                float mu = s + bqm[o];
                muS[b*16+o] = mu;
                if (nt == 0) out_mu[((size_t)gb*T_+t)*ZD_+o] = mu;
            } else {
                int oj = o - 16;
                float sd = softplusf_(s + bqs[oj]) + 1e-4f;
                sdS[b*16+oj] = sd;
                if (nt == 0) out_std[((size_t)gb*T_+t)*ZD_+oj] = sd;
            }
        }
        __syncthreads();
        if (tid < 64){
            int b = tid, gb = mt*64 + b;
            float z[ZD_];
#pragma unroll
            for (int d=0; d<ZD_; d++)
                z[d] = muS[b*16+d] + eps[((size_t)gb*T_+t)*ZD_+d]*sdS[b*16+d];
            float ld = 0.f;
#pragma unroll
            for (int k=0;k<L_;k++){
                float dot = 0.f;
                for (int i=0;i<ZD_;i++) dot = fmaf(z[i], fw[k*ZD_+i], dot);
                float hh = tanhf(dot + fb[k]);
                float psiu = 0.f;
                for (int i=0;i<ZD_;i++){
                    z[i] += g_uhat[k*ZD_+i]*hh;
                    psiu = fmaf((1.f - hh*hh)*fw[k*ZD_+i], g_uhat[k*ZD_+i], psiu);
                }
                ld += logf(fabsf(1.f + psiu) + 1e-6f);
            }
#pragma unroll
            for (int d=0; d<ZD_; d++) zzS[b*17+d] = z[d];
            if (nt == 0){
#pragma unroll
                for (int d=0; d<ZD_; d++) out_z[((size_t)gb*T_+t)*ZD_+d] = z[d];
                out_ld[gb] += ld;
            }
        }
        // ---------- input-projection weights/biases for p combine ----------
        for (int idx = tid; idx < ZD_*192; idx += 256){
            int d = idx & 15, col = idx >> 4;
            int gg = col >> 6, jj = col & 63;
            int j = nt*64 + jj;
            wpS[d*192 + col] = (j < 500) ? Wihp[((size_t)(gg*500 + j))*ZD_ + d] : 0.f;
        }
        {
            int q4 = tid >> 6, jj = tid & 63;
            int j = nt*64 + jj;
            float v = 0.f;
            if (j < 500){
                if (q4 == 0) v = bihp[j]       + bhhp[j];
                else if (q4 == 1) v = bihp[500+j]  + bhhp[500+j];
                else if (q4 == 2) v = bihp[1000+j];
                else v = bhhp[1000+j];
            }
            bspS[q4*64 + jj] = v;
        }
    }
    __syncthreads();

    float acc[3][2][2][4];
#pragma unroll
    for (int a=0;a<3;a++)
#pragma unroll
        for (int i=0;i<2;i++)
#pragma unroll
            for (int j=0;j<2;j++)
#pragma unroll
                for (int c=0;c<4;c++) acc[a][i][j][c]=0.f;

    int g = lane >> 3, l = lane & 7;
    int a_row = wm*32 + (g&1)*8 + l;
    int a_kb  = (g>>1)*16;
    int b_row = wn*16 + (g>>1)*8 + l;
    int b_kb  = (g&1)*16;

    for (int ch=0; ch<CH_; ch++){
        if (ch+1 < CH_){ copy_chunk(ch+1,(ch+1)&1); cp_commit(); cp_wait<1>(); }
        else cp_wait<0>();
        __syncthreads();

        uint32_t Ahi_b = sbase + (ch&1)*40960;
        uint32_t Alo_b = Ahi_b + 8192;
        uint32_t Bb    = Ahi_b + 16384;

#pragma unroll
        for (int s=0; s<4; s++){
            uint32_t Ah[2][4], Al[2][4], Bf[3][2][2];
            uint32_t a_off = swz128((uint32_t)(a_row*128 + s*32 + a_kb));
            uint32_t b_off = swz128((uint32_t)(b_row*128 + s*32 + b_kb));
#pragma unroll
            for (int mi=0; mi<2; mi++){
                uint32_t ao = a_off + mi*2048;
                ldsm_x4(Ah[mi][0],Ah[mi][1],Ah[mi][2],Ah[mi][3], Ahi_b + ao);
                ldsm_x4(Al[mi][0],Al[mi][1],Al[mi][2],Al[mi][3], Alo_b + ao);
            }
#pragma unroll
            for (int g3=0; g3<3; g3++){
                uint32_t r0,r1,r2,r3;
                ldsm_x4(r0,r1,r2,r3, Bb + g3*8192 + b_off);
                Bf[g3][0][0]=r0; Bf[g3][0][1]=r1; Bf[g3][1][0]=r2; Bf[g3][1][1]=r3;
            }
#pragma unroll
            for (int g3=0; g3<3; g3++)
#pragma unroll
                for (int mi=0; mi<2; mi++)
#pragma unroll
                    for (int ni=0; ni<2; ni++){
                        mma_fp16(acc[g3][mi][ni], Ah[mi], Bf[g3][ni]);
                        mma_fp16(acc[g3][mi][ni], Al[mi], Bf[g3][ni]);
                    }
        }
        __syncthreads();
    }

    // -------- epilogue: GRU combine in registers --------
    float* hqS = (float*)tiles;              // q: [64][65]
    int rr = lane>>2, cc = (lane&3)*2;
#pragma unroll
    for (int mi=0; mi<2; mi++){
#pragma unroll
        for (int hh=0; hh<2; hh++){
            int mrow = wm*32 + mi*16 + hh*8 + rr;
            int b = mt*64 + mrow;
            float zr[ZD_];
            if (gru){
#pragma unroll
                for (int d=0; d<ZD_; d++) zr[d] = zzS[mrow*17 + d];
            }
#pragma unroll
            for (int ni=0; ni<2; ni++){
                int jj = wn*16 + ni*8 + cc;
                int j = nt*64 + jj;
                if (j >= 500){
                    if (!gru){ hqS[mrow*65+jj] = 0.f; hqS[mrow*65+jj+1] = 0.f; }
                    continue;
                }
                float xw0[3], xw1[3];
                if (!gru){
                    size_t base = ((size_t)b*T_ + t)*NG + j;
#pragma unroll
                    for (int g3=0; g3<3; g3++){
                        __half2 hv = *(const __half2*)&g_Gx[base + g3*512];
                        xw0[g3] = __low2float(hv);
                        xw1[g3] = __high2float(hv);
                    }
                } else {
#pragma unroll
                    for (int g3=0; g3<3; g3++){
                        float s0 = bspS[g3*64 + jj];
                        float s1 = bspS[g3*64 + jj + 1];
#pragma unroll
                        for (int d=0; d<ZD_; d++){
                            float zv = zr[d];
                            s0 = fmaf(zv, wpS[d*192 + g3*64 + jj],     s0);
                            s1 = fmaf(zv, wpS[d*192 + g3*64 + jj + 1], s1);
                        }
                        xw0[g3] = s0; xw1[g3] = s1;
                    }
                }
                float bn0 = gru ? bspS[3*64 + jj]     : bnnS[jj];
                float bn1 = gru ? bspS[3*64 + jj + 1] : bnnS[jj + 1];
                float aR0 = acc[0][mi][ni][hh*2+0], aR1 = acc[0][mi][ni][hh*2+1];
                float aZ0 = acc[1][mi][ni][hh*2+0], aZ1 = acc[1][mi][ni][hh*2+1];
                float aN0 = acc[2][mi][ni][hh*2+0], aN1 = acc[2][mi][ni][hh*2+1];

                float2 hp = *(float2*)&g_h[(size_t)(gru*1024 + b)*HP + j];
                float r0 = sigmoidf_(xw0[0] + aR0);
                float r1 = sigmoidf_(xw1[0] + aR1);
                float z0 = sigmoidf_(xw0[1] + aZ0);
                float z1 = sigmoidf_(xw1[1] + aZ1);
                float n0 = tanhf(xw0[2] + r0*(aN0 + bn0));
                float n1 = tanhf(xw1[2] + r1*(aN1 + bn1));
                float h0 = (1.f - z0)*n0 + z0*hp.x;
                float h1 = (1.f - z1)*n1 + z1*hp.y;

                *(float2*)&g_h[(size_t)(gru*1024 + b)*HP + j] = make_float2(h0, h1);

                __half2 hi2 = __floats2half2_rn(h0, h1);
                __half2 lo2 = __floats2half2_rn(h0 - __low2float(hi2), h1 - __high2float(hi2));
                uint32_t sw = swz128((uint32_t)(mrow*128 + (j&63)*2));
                *(__half2*)(g_Ah + a_img(gru, par_w, mt, 0, j>>6) + sw) = hi2;
                *(__half2*)(g_Ah + a_img(gru, par_w, mt, 1, j>>6) + sw) = lo2;

                if (gru){
                    *(float2*)&g_hist[((size_t)b*T_ + t)*HP + j] = make_float2(h0, h1);
                } else {
                    hqS[mrow*65+jj]   = h0;
                    hqS[mrow*65+jj+1] = h1;
                }
            }
        }
    }

    // -------- q role: mu/std partials for step t --------
    if (!gru){
        float* WqS = (float*)(tiles + 20480);   // [64][32] as [j][o]
        __syncthreads();
        for (int idx = tid; idx < 64*32; idx += 256){
            int j = idx >> 5, o = idx & 31;
            int gj = nt*64 + j;
            float v = 0.f;
            if (gj < H_)
                v = (o < 16) ? Wqm[o*(H_+ZD_) + gj] : Wqs[(o-16)*(H_+ZD_) + gj];
            WqS[j*32+o] = v;
        }
        __syncthreads();
        for (int idx = tid; idx < 64*32; idx += 256){
            int b = idx >> 5, o = idx & 31;
            float s = 0.f;
#pragma unroll
            for (int j=0;j<64;j++)
                s = fmaf(hqS[b*65+j], WqS[j*32+o], s);
            g_part[t&1][nt][mt*64+b][o] = s;
        }
    }
}

// ----------------------------- post-loop: all reconstructions ----------------
__global__ __launch_bounds__(256)
void recon_all(const float* __restrict__ Wpm, const float* __restrict__ bpm,
               const float* __restrict__ Wps, const float* __restrict__ bps,
               float* __restrict__ out_rm, float* __restrict__ out_rs){
    extern __shared__ float hs[];    // [RROWS][HP]
    int m0 = blockIdx.x * RROWS;
    int tid = threadIdx.x, w = tid>>5, lane = tid&31;
#pragma unroll
    for (int k=0;k<RROWS*128/256;k++){
        int idx = k*256 + tid;
        int r = idx >> 7, q4 = idx & 127;
        ((float4*)&hs[r*HP])[q4] = ((const float4*)&g_hist[(size_t)(m0+r)*HP])[q4];
    }
    __syncthreads();
    for (int o = w; o < 2*XD_; o += 8){
        int d = (o < XD_) ? o : o - XD_;
        const float* Wrow = ((o < XD_) ? Wpm : Wps) + (size_t)d*H_;
        for (int r=0;r<RROWS;r++){
            float acc = 0.f;
            for (int i=lane; i<H_; i+=32) acc = fmaf(hs[r*HP+i], Wrow[i], acc);
#pragma unroll
            for (int off=16; off; off>>=1) acc += __shfl_down_sync(0xFFFFFFFFu, acc, off);
            if (lane == 0){
                size_t oidx = (size_t)(m0+r)*XD_ + d;
                if (o < XD_) out_rm[oidx] = acc + bpm[d];
                else         out_rs[oidx] = softplusf_(acc + bps[d]) + 1e-4f;
            }
        }
    }
}

// ----------------------------- launcher --------------------------------------
extern "C" void kernel_launch(void* const* d_in, const int* in_sizes, int n_in,
                              void* d_out, int out_size){
    const float* x     = (const float*)d_in[0];
    const float* eps   = (const float*)d_in[1];
    const float* Wih_q = (const float*)d_in[2];
    const float* Whh_q = (const float*)d_in[3];
    const float* bih_q = (const float*)d_in[4];
    const float* bhh_q = (const float*)d_in[5];
    const float* Wqm   = (const float*)d_in[6];
    const float* bqm   = (const float*)d_in[7];
    const float* Wqs   = (const float*)d_in[8];
    const float* bqs   = (const float*)d_in[9];
    const float* Wih_p = (const float*)d_in[10];
    const float* Whh_p = (const float*)d_in[11];
    const float* bih_p = (const float*)d_in[12];
    const float* bhh_p = (const float*)d_in[13];
    const float* Wpm   = (const float*)d_in[14];
    const float* bpm   = (const float*)d_in[15];
    const float* Wps   = (const float*)d_in[16];
    const float* bps   = (const float*)d_in[17];
    const float* fu    = (const float*)d_in[18];
    const float* fw    = (const float*)d_in[19];
    const float* fb    = (const float*)d_in[20];

    float* out = (float*)d_out;
    float* out_rm  = out;
    float* out_rs  = out_rm  + (size_t)B_*T_*XD_;
    float* out_z   = out_rs  + (size_t)B_*T_*XD_;
    float* out_mu  = out_z   + (size_t)B_*T_*ZD_;
    float* out_std = out_mu  + (size_t)B_*T_*ZD_;
    float* out_ld  = out_std + (size_t)B_*T_*ZD_;

    cudaFuncSetAttribute(gru_pq,    cudaFuncAttributeMaxDynamicSharedMemorySize, SMEM_GRU);
    cudaFuncSetAttribute(gx_gemm,   cudaFuncAttributeMaxDynamicSharedMemorySize, SMEM_GX);
    cudaFuncSetAttribute(recon_all, cudaFuncAttributeMaxDynamicSharedMemorySize, SMEM_RC);

    init_kernel<<<1024,256>>>(out_ld, fu, fw);
    stage_whh<<<(2*G3H*H_+255)/256,256>>>(Whh_q, Whh_p);
    stage_x_wih<<<(B_*T_*XD_ + G3H*XD_ + 255)/256,256>>>(x, Wih_q);
    gx_gemm<<<dim3(GXNT, GXMT),256,SMEM_GX>>>(bih_q, bhh_q);

    dim3 pq_grid(NT_G, 32);   // 8 x 32 = 256 CTAs (p-half + q-half)

    // prologue: q(0) only (writes hq(0) into parity 0 + mu/std partials for t=0)
    gru_pq<<<pq_grid,256,SMEM_GRU>>>(0, 0, 0, 1, eps, Wih_p, bih_p, bhh_p, bhh_q,
                                     Wqm, bqm, Wqs, bqs, fw, fb,
                                     out_z, out_mu, out_std, out_ld);

    for (int t=0; t<T_; t++){
        // ONE launch: z(t) [flows, in p-CTAs] + p(t) + q(t+1)
        gru_pq<<<pq_grid,256,SMEM_GRU>>>(t, 1, t+1, (t+1 < T_) ? 1 : 0,
                                         eps, Wih_p, bih_p, bhh_p, bhh_q,
                                         Wqm, bqm, Wqs, bqs, fw, fb,
                                         out_z, out_mu, out_std, out_ld);
    }
    recon_all<<<(B_*T_)/RROWS,256,SMEM_RC>>>(Wpm, bpm, Wps, bps, out_rm, out_rs);
}

// round 11
// speedup vs baseline: 2.4106x; 1.0002x over previous
#include <cuda_runtime.h>
#include <cuda_fp16.h>
#include <math.h>
#include <stdint.h>

#define B_   1024
#define T_   100
#define XD_  38
#define H_   500
#define ZD_  16
#define L_   3
#define G3H  1500
#define HP   512
#define NG   1536
#define MT_G 16
#define NT_G 8
#define CH_  8
#define AIMG 8192
#define BIMG 8192
#define GXMT 800
#define GXNT 24
#define RROWS 32
#define NCTA_P 256
#define SMEM_P   101632
#define SMEM_GX  41984
#define SMEM_RC  65536

// ----------------------------- device scratch --------------------------------
__device__ __align__(1024) float   g_h[(size_t)2*B_*HP];
__device__ __align__(1024) uint8_t g_Ah[(size_t)2*2*MT_G*2*CH_*AIMG]; // [gru][par][mt][split][ch]
__device__ __align__(1024) uint8_t g_Bw[(size_t)2*NT_G*3*CH_*BIMG];
__device__ __align__(1024) uint8_t g_Ax[(size_t)GXMT*2*16384];
__device__ __align__(1024) uint8_t g_Bx[(size_t)GXNT*BIMG];
__device__ __align__(1024) __half  g_Gx[(size_t)B_*T_*NG];
__device__ __align__(1024) float   g_hist[(size_t)B_*T_*HP];
__device__ float g_part[2][NT_G][B_][32];
__device__ float g_uhat[L_*ZD_];
__device__ unsigned g_bar_count;
__device__ volatile unsigned g_bar_gen;

// ----------------------------- helpers ---------------------------------------
__device__ __forceinline__ float sigmoidf_(float x){ return 1.0f/(1.0f+expf(-x)); }
__device__ __forceinline__ float softplusf_(float x){ return (x>20.0f)? x : log1pf(expf(x)); }
__device__ __forceinline__ uint32_t swz128(uint32_t off){ return off ^ ((off>>3)&0x70); }

__device__ __forceinline__ size_t a_img(int gru,int par,int mt,int split,int ch){
    return (((((size_t)gru*2 + par)*MT_G + mt)*2 + split)*CH_ + ch)*AIMG;
}
__device__ __forceinline__ size_t b_img(int gru,int nt,int gate,int ch){
    return ((((size_t)gru*NT_G + nt)*3 + gate)*CH_ + ch)*BIMG;
}
__device__ __forceinline__ uint32_t smem_u32(const void* p){
    uint32_t a;
    asm("{ .reg .u64 t; cvta.to.shared.u64 t, %1; cvt.u32.u64 %0, t; }" : "=r"(a) : "l"(p));
    return a;
}
__device__ __forceinline__ void cp_async16(uint32_t dst, const void* src){
    asm volatile("cp.async.cg.shared.global [%0], [%1], 16;" :: "r"(dst), "l"(src));
}
__device__ __forceinline__ void cp_commit(){ asm volatile("cp.async.commit_group;" ::: "memory"); }
template<int N>
__device__ __forceinline__ void cp_wait(){ asm volatile("cp.async.wait_group %0;" :: "n"(N) : "memory"); }
__device__ __forceinline__ void ldsm_x4(uint32_t& r0, uint32_t& r1, uint32_t& r2, uint32_t& r3, uint32_t addr){
    asm volatile("ldmatrix.sync.aligned.m8n8.x4.shared.b16 {%0,%1,%2,%3}, [%4];"
                 : "=r"(r0), "=r"(r1), "=r"(r2), "=r"(r3) : "r"(addr));
}
__device__ __forceinline__ void mma_fp16(float* c, const uint32_t* a, const uint32_t* b){
    asm volatile("mma.sync.aligned.m16n8k16.row.col.f32.f16.f16.f32 "
                 "{%0,%1,%2,%3}, {%4,%5,%6,%7}, {%8,%9}, {%0,%1,%2,%3};"
                 : "+f"(c[0]), "+f"(c[1]), "+f"(c[2]), "+f"(c[3])
                 : "r"(a[0]), "r"(a[1]), "r"(a[2]), "r"(a[3]), "r"(b[0]), "r"(b[1]));
}
__device__ __forceinline__ void grid_barrier(unsigned &gen){
    __syncthreads();
    gen++;
    if (threadIdx.x == 0){
        __threadfence();
        unsigned prev = atomicAdd(&g_bar_count, 1u);
        if (prev == gen*NCTA_P - 1u){
            __threadfence();
            g_bar_gen = gen;
        } else {
            while (g_bar_gen < gen) __nanosleep(64);
        }
    }
    __syncthreads();
    __threadfence();
}

// ----------------------------- setup launch 1: init --------------------------
__global__ void init_kernel(float* __restrict__ out_ld,
                            const float* __restrict__ fu, const float* __restrict__ fw){
    size_t i = (size_t)blockIdx.x*blockDim.x + threadIdx.x;
    size_t stride = (size_t)gridDim.x*blockDim.x;
    float4* h4 = (float4*)g_h;
    for (size_t k=i; k<sizeof(g_h)/16;  k+=stride) h4[k] = make_float4(0,0,0,0);
    uint4* p;
    p = (uint4*)g_Ah; for (size_t k=i; k<sizeof(g_Ah)/16; k+=stride) p[k] = make_uint4(0,0,0,0);
    p = (uint4*)g_Bw; for (size_t k=i; k<sizeof(g_Bw)/16; k+=stride) p[k] = make_uint4(0,0,0,0);
    p = (uint4*)g_Ax; for (size_t k=i; k<sizeof(g_Ax)/16; k+=stride) p[k] = make_uint4(0,0,0,0);
    p = (uint4*)g_Bx; for (size_t k=i; k<sizeof(g_Bx)/16; k+=stride) p[k] = make_uint4(0,0,0,0);
    for (size_t k=i; k<B_; k+=stride) out_ld[k]=0.f;
    if (i == 0){ g_bar_count = 0; g_bar_gen = 0; }
    if (i < L_){
        int k = (int)i;
        float wu=0.f, ww=0.f;
        for (int j=0;j<ZD_;j++){ wu += fw[k*ZD_+j]*fu[k*ZD_+j]; ww += fw[k*ZD_+j]*fw[k*ZD_+j]; }
        float m = -1.0f + softplusf_(wu);
        float scale = (m - wu)/(ww + 1e-6f);
        for (int j=0;j<ZD_;j++) g_uhat[k*ZD_+j] = fu[k*ZD_+j] + scale*fw[k*ZD_+j];
    }
}

// ----------------------------- setup launch 2: stage both Whh ----------------
__global__ void stage_whh(const float* __restrict__ Wq, const float* __restrict__ Wp){
    int idx = blockIdx.x*blockDim.x + threadIdx.x;
    if (idx >= 2*G3H*H_) return;
    int gru = idx / (G3H*H_);
    int rem = idx - gru*(G3H*H_);
    int n = rem / H_, k = rem - n*H_;
    float v = (gru ? Wp : Wq)[n*H_ + k];
    int gate = n / 500, j = n - gate*500;
    int nt = j>>6, r = j&63, ch = k>>6, c = k&63;
    *(__half*)(g_Bw + b_img(gru,nt,gate,ch) + swz128((uint32_t)(r*128 + c*2))) = __float2half_rn(v);
}

// ----------------------------- setup launch 3: stage x (split) + Wih_q -------
__global__ void stage_x_wih(const float* __restrict__ x, const float* __restrict__ Wih_q){
    int idx = blockIdx.x*blockDim.x + threadIdx.x;
    const int NX = B_*T_*XD_;
    if (idx < NX){
        int m = idx / XD_, d = idx - m*XD_;
        float v = x[idx];
        int mt = m>>7, r = m&127;
        uint32_t sw = swz128((uint32_t)(r*128 + d*2));
        __half hi = __float2half_rn(v);
        __half lo = __float2half_rn(v - __half2float(hi));
        *(__half*)(g_Ax + (size_t)(mt*2+0)*16384 + sw) = hi;
        *(__half*)(g_Ax + (size_t)(mt*2+1)*16384 + sw) = lo;
    } else if (idx < NX + G3H*XD_){
        int e = idx - NX;
        int n = e / XD_, d = e - n*XD_;
        int gate = n / 500, j = n - gate*500;
        int ni = gate*512 + j;
        int nt = ni>>6, r = ni&63;
        *(__half*)(g_Bx + (size_t)nt*BIMG + swz128((uint32_t)(r*128 + d*2))) =
            __float2half_rn(Wih_q[n*XD_ + d]);
    }
}

// ----------------------------- setup launch 4: Gx = x @ Wih_q^T + bias -------
__global__ __launch_bounds__(256)
void gx_gemm(const float* __restrict__ bih, const float* __restrict__ bhh){
    extern __shared__ uint8_t smem_raw[];
    uint8_t* tiles = (uint8_t*)(((uintptr_t)smem_raw + 1023) & ~(uintptr_t)1023);
    uint32_t sbase = smem_u32(tiles);
    int tid = threadIdx.x, wid = tid>>5, lane = tid&31;
    int nt = blockIdx.x, mt = blockIdx.y;
    int wm = wid & 1, wn = wid >> 1;

    {
        const uint8_t* sa0 = g_Ax + (size_t)(mt*2+0)*16384;
        const uint8_t* sa1 = g_Ax + (size_t)(mt*2+1)*16384;
        const uint8_t* sb  = g_Bx + (size_t)nt*BIMG;
#pragma unroll
        for (int r=0;r<10;r++){
            int idx = r*256 + tid;
            if (idx < 1024)      cp_async16(sbase + idx*16, sa0 + idx*16);
            else if (idx < 2048) cp_async16(sbase + 16384 + (idx-1024)*16, sa1 + (idx-1024)*16);
            else                 cp_async16(sbase + 32768 + (idx-2048)*16, sb + (idx-2048)*16);
        }
    }
    cp_commit(); cp_wait<0>(); __syncthreads();

    float acc[4][2][4];
#pragma unroll
    for (int i=0;i<4;i++)
#pragma unroll
        for (int j=0;j<2;j++)
#pragma unroll
            for (int c=0;c<4;c++) acc[i][j][c]=0.f;

    int g = lane >> 3, l = lane & 7;
    int a_row = wm*64 + (g&1)*8 + l;
    int a_kb  = (g>>1)*16;
    int b_row = wn*16 + (g>>1)*8 + l;
    int b_kb  = (g&1)*16;

#pragma unroll
    for (int s=0; s<4; s++){
        uint32_t Ah[4][4], Al[4][4], Bf[2][2];
        uint32_t a_off = swz128((uint32_t)(a_row*128 + s*32 + a_kb));
        uint32_t b_off = swz128((uint32_t)(b_row*128 + s*32 + b_kb));
#pragma unroll
        for (int mi=0; mi<4; mi++){
            uint32_t ao = a_off + mi*2048;
            ldsm_x4(Ah[mi][0],Ah[mi][1],Ah[mi][2],Ah[mi][3], sbase + ao);
            ldsm_x4(Al[mi][0],Al[mi][1],Al[mi][2],Al[mi][3], sbase + 16384 + ao);
        }
        {
            uint32_t r0,r1,r2,r3;
            ldsm_x4(r0,r1,r2,r3, sbase + 32768 + b_off);
            Bf[0][0]=r0; Bf[0][1]=r1; Bf[1][0]=r2; Bf[1][1]=r3;
        }
#pragma unroll
        for (int mi=0; mi<4; mi++)
#pragma unroll
            for (int ni=0; ni<2; ni++){
                mma_fp16(acc[mi][ni], Ah[mi], Bf[ni]);
                mma_fp16(acc[mi][ni], Al[mi], Bf[ni]);
            }
    }

    int rr = lane>>2, cc = (lane&3)*2;
#pragma unroll
    for (int mi=0; mi<4; mi++){
#pragma unroll
        for (int ni=0; ni<2; ni++){
#pragma unroll
            for (int hh=0; hh<2; hh++){
                int m = mt*128 + wm*64 + mi*16 + hh*8 + rr;
                int n = nt*64 + wn*16 + ni*8 + cc;
                int gate = n>>9, j = n&511;
                float v0 = acc[mi][ni][hh*2+0];
                float v1 = acc[mi][ni][hh*2+1];
                if (j+1 < 500){
                    float b0 = bih[gate*500+j]   + (gate<2 ? bhh[gate*500+j]   : 0.f);
                    float b1 = bih[gate*500+j+1] + (gate<2 ? bhh[gate*500+j+1] : 0.f);
                    v0 += b0; v1 += b1;
                }
                *(__half2*)&g_Gx[(size_t)m*NG + n] = __floats2half2_rn(v0, v1);
            }
        }
    }
}

// ----------------------------- persistent stepped kernel ---------------------
// grid (8, 32): y<16 -> p-role (gru=1), y>=16 -> q-role (gru=0).
// iteration it: p runs t=it (it>=0), q runs t=it+1 (it+1<T). Grid barrier per it.
__global__ __launch_bounds__(256,2)
void gru_persist(const float* __restrict__ eps,
                 const float* __restrict__ Wihp,
                 const float* __restrict__ bihp, const float* __restrict__ bhhp,
                 const float* __restrict__ bhhq,
                 const float* __restrict__ Wqm, const float* __restrict__ bqm,
                 const float* __restrict__ Wqs, const float* __restrict__ bqs,
                 const float* __restrict__ fw, const float* __restrict__ fb,
                 float* __restrict__ out_z, float* __restrict__ out_mu,
                 float* __restrict__ out_std, float* __restrict__ out_ld){
    int role = blockIdx.y >> 4;
    int gru  = role ? 0 : 1;            // 1 = p, 0 = q
    int nt = blockIdx.x, mt = blockIdx.y & 15;

    extern __shared__ uint8_t smem_raw[];
    uint8_t* tiles = (uint8_t*)(((uintptr_t)smem_raw + 1023) & ~(uintptr_t)1023);
    uint32_t sbase = smem_u32(tiles);
    // persistent high region (above 2x40KB tile buffers)
    float* zzS  = (float*)(tiles + 81920);   // p: [64][17] per-step
    float* wpS  = (float*)(tiles + 86272);   // p: [16][192] static
    float* bspS = (float*)(tiles + 98560);   // p: [4][64]  static
    float* WzS  = (float*)(tiles + 99584);   // p: [16][32] static
    float* bnnS = (float*)(tiles + 81920);   // q: [64]     static
    float* WqS  = (float*)(tiles + 82176);   // q: [64][32] static

    int tid = threadIdx.x, wid = tid>>5, lane = tid&31;
    int wm = wid & 1, wn = wid >> 1;

    // ---- one-time staging of time-invariant data ----
    if (!gru){
        if (tid < 64){
            int j = nt*64 + tid;
            bnnS[tid] = (j < 500) ? bhhq[1000 + j] : 0.f;
        }
        for (int idx = tid; idx < 64*32; idx += 256){
            int j = idx >> 5, o = idx & 31;
            int gj = nt*64 + j;
            float v = 0.f;
            if (gj < H_)
                v = (o < 16) ? Wqm[o*(H_+ZD_) + gj] : Wqs[(o-16)*(H_+ZD_) + gj];
            WqS[j*32+o] = v;
        }
    } else {
        for (int idx = tid; idx < ZD_*192; idx += 256){
            int d = idx & 15, col = idx >> 4;
            int gg = col >> 6, jj = col & 63;
            int j = nt*64 + jj;
            wpS[d*192 + col] = (j < 500) ? Wihp[((size_t)(gg*500 + j))*ZD_ + d] : 0.f;
        }
        {
            int q4 = tid >> 6, jj = tid & 63;
            int j = nt*64 + jj;
            float v = 0.f;
            if (j < 500){
                if (q4 == 0) v = bihp[j]       + bhhp[j];
                else if (q4 == 1) v = bihp[500+j]  + bhhp[500+j];
                else if (q4 == 2) v = bihp[1000+j];
                else v = bhhp[1000+j];
            }
            bspS[q4*64 + jj] = v;
        }
        for (int idx = tid; idx < 16*32; idx += 256){
            int d = idx >> 5, o = idx & 31;
            WzS[idx] = (o < 16) ? Wqm[o*(H_+ZD_) + H_ + d]
                                : Wqs[(o-16)*(H_+ZD_) + H_ + d];
        }
    }
    __syncthreads();

    int g = lane >> 3, l = lane & 7;
    int a_row = wm*32 + (g&1)*8 + l;
    int a_kb  = (g>>1)*16;
    int b_row = wn*16 + (g>>1)*8 + l;
    int b_kb  = (g&1)*16;
    int rr = lane>>2, cc = (lane&3)*2;

    unsigned gen = 0;

    for (int it = -1; it < T_; ++it){
        int t = gru ? it : (it + 1);
        bool active = gru ? (it >= 0) : (it + 1 < T_);
        if (active){
            int par_w = t & 1;
            int par_r = par_w ^ 1;

            auto copy_chunk = [&](int ch, int buf){
                const uint8_t* srcs[5] = {
                    g_Ah + a_img(gru,par_r,mt,0,ch), g_Ah + a_img(gru,par_r,mt,1,ch),
                    g_Bw + b_img(gru,nt,0,ch), g_Bw + b_img(gru,nt,1,ch), g_Bw + b_img(gru,nt,2,ch)
                };
                uint32_t dbase = sbase + buf*40960;
#pragma unroll
                for (int r=0;r<10;r++){
                    int idx = r*256 + tid;
                    int img = idx >> 9;
                    int off = (idx & 511)*16;
                    cp_async16(dbase + img*8192 + off, srcs[img] + off);
                }
            };

            copy_chunk(0,0); cp_commit();

            if (gru){
                // ---------- p prologue: z(t) from partials + flows ----------
                float* zpS = (float*)(tiles + 40960);   // [64][16] (buffer-1 scratch)
                float* muS = (float*)(tiles + 47104);   // [64][16]
                float* sdS = (float*)(tiles + 51200);   // [64][16]
                for (int idx = tid; idx < 64*16; idx += 256){
                    int r = idx >> 4, d = idx & 15;
                    zpS[idx] = (t==0) ? 0.f : out_z[((size_t)(mt*64+r)*T_ + (t-1))*ZD_ + d];
                }
                __syncthreads();
                for (int idx = tid; idx < 64*32; idx += 256){
                    int b = idx >> 5, o = idx & 31;
                    int gb = mt*64 + b;
                    float s = 0.f;
#pragma unroll
                    for (int q8 = 0; q8 < NT_G; q8++) s += g_part[t&1][q8][gb][o];
#pragma unroll
                    for (int d = 0; d < ZD_; d++) s = fmaf(zpS[b*16+d], WzS[d*32+o], s);
                    if (o < 16){
                        float mu = s + bqm[o];
                        muS[b*16+o] = mu;
                        if (nt == 0) out_mu[((size_t)gb*T_+t)*ZD_+o] = mu;
                    } else {
                        int oj = o - 16;
                        float sd = softplusf_(s + bqs[oj]) + 1e-4f;
                        sdS[b*16+oj] = sd;
                        if (nt == 0) out_std[((size_t)gb*T_+t)*ZD_+oj] = sd;
                    }
                }
                __syncthreads();
                if (tid < 64){
                    int b = tid, gb = mt*64 + b;
                    float z[ZD_];
#pragma unroll
                    for (int d=0; d<ZD_; d++)
                        z[d] = muS[b*16+d] + eps[((size_t)gb*T_+t)*ZD_+d]*sdS[b*16+d];
                    float ld = 0.f;
#pragma unroll
                    for (int k=0;k<L_;k++){
                        float dot = 0.f;
                        for (int i=0;i<ZD_;i++) dot = fmaf(z[i], fw[k*ZD_+i], dot);
                        float hh = tanhf(dot + fb[k]);
                        float psiu = 0.f;
                        for (int i=0;i<ZD_;i++){
                            z[i] += g_uhat[k*ZD_+i]*hh;
                            psiu = fmaf((1.f - hh*hh)*fw[k*ZD_+i], g_uhat[k*ZD_+i], psiu);
                        }
                        ld += logf(fabsf(1.f + psiu) + 1e-6f);
                    }
#pragma unroll
                    for (int d=0; d<ZD_; d++) zzS[b*17+d] = z[d];
                    if (nt == 0){
#pragma unroll
                        for (int d=0; d<ZD_; d++) out_z[((size_t)gb*T_+t)*ZD_+d] = z[d];
                        out_ld[gb] += ld;
                    }
                }
            }
            __syncthreads();

            float acc[3][2][2][4];
#pragma unroll
            for (int a=0;a<3;a++)
#pragma unroll
                for (int i=0;i<2;i++)
#pragma unroll
                    for (int j=0;j<2;j++)
#pragma unroll
                        for (int c=0;c<4;c++) acc[a][i][j][c]=0.f;

            for (int ch=0; ch<CH_; ch++){
                if (ch+1 < CH_){ copy_chunk(ch+1,(ch+1)&1); cp_commit(); cp_wait<1>(); }
                else cp_wait<0>();
                __syncthreads();

                uint32_t Ahi_b = sbase + (ch&1)*40960;
                uint32_t Alo_b = Ahi_b + 8192;
                uint32_t Bb    = Ahi_b + 16384;

#pragma unroll
                for (int s=0; s<4; s++){
                    uint32_t Ah[2][4], Al[2][4], Bf[3][2][2];
                    uint32_t a_off = swz128((uint32_t)(a_row*128 + s*32 + a_kb));
                    uint32_t b_off = swz128((uint32_t)(b_row*128 + s*32 + b_kb));
#pragma unroll
                    for (int mi=0; mi<2; mi++){
                        uint32_t ao = a_off + mi*2048;
                        ldsm_x4(Ah[mi][0],Ah[mi][1],Ah[mi][2],Ah[mi][3], Ahi_b + ao);
                        ldsm_x4(Al[mi][0],Al[mi][1],Al[mi][2],Al[mi][3], Alo_b + ao);
                    }
#pragma unroll
                    for (int g3=0; g3<3; g3++){
                        uint32_t r0,r1,r2,r3;
                        ldsm_x4(r0,r1,r2,r3, Bb + g3*8192 + b_off);
                        Bf[g3][0][0]=r0; Bf[g3][0][1]=r1; Bf[g3][1][0]=r2; Bf[g3][1][1]=r3;
                    }
#pragma unroll
                    for (int g3=0; g3<3; g3++)
#pragma unroll
                        for (int mi=0; mi<2; mi++)
#pragma unroll
                            for (int ni=0; ni<2; ni++){
                                mma_fp16(acc[g3][mi][ni], Ah[mi], Bf[g3][ni]);
                                mma_fp16(acc[g3][mi][ni], Al[mi], Bf[g3][ni]);
                            }
                }
                __syncthreads();
            }

            // -------- epilogue: GRU combine in registers --------
            float* hqS = (float*)tiles;              // q: [64][65]
#pragma unroll
            for (int mi=0; mi<2; mi++){
#pragma unroll
                for (int hh=0; hh<2; hh++){
                    int mrow = wm*32 + mi*16 + hh*8 + rr;
                    int b = mt*64 + mrow;
                    float zr[ZD_];
                    if (gru){
#pragma unroll
                        for (int d=0; d<ZD_; d++) zr[d] = zzS[mrow*17 + d];
                    }
#pragma unroll
                    for (int ni=0; ni<2; ni++){
                        int jj = wn*16 + ni*8 + cc;
                        int j = nt*64 + jj;
                        if (j >= 500){
                            if (!gru){ hqS[mrow*65+jj] = 0.f; hqS[mrow*65+jj+1] = 0.f; }
                            continue;
                        }
                        float xw0[3], xw1[3];
                        if (!gru){
                            size_t base = ((size_t)b*T_ + t)*NG + j;
#pragma unroll
                            for (int g3=0; g3<3; g3++){
                                __half2 hv = *(const __half2*)&g_Gx[base + g3*512];
                                xw0[g3] = __low2float(hv);
                                xw1[g3] = __high2float(hv);
                            }
                        } else {
#pragma unroll
                            for (int g3=0; g3<3; g3++){
                                float s0 = bspS[g3*64 + jj];
                                float s1 = bspS[g3*64 + jj + 1];
#pragma unroll
                                for (int d=0; d<ZD_; d++){
                                    float zv = zr[d];
                                    s0 = fmaf(zv, wpS[d*192 + g3*64 + jj],     s0);
                                    s1 = fmaf(zv, wpS[d*192 + g3*64 + jj + 1], s1);
                                }
                                xw0[g3] = s0; xw1[g3] = s1;
                            }
                        }
                        float bn0 = gru ? bspS[3*64 + jj]     : bnnS[jj];
                        float bn1 = gru ? bspS[3*64 + jj + 1] : bnnS[jj + 1];
                        float aR0 = acc[0][mi][ni][hh*2+0], aR1 = acc[0][mi][ni][hh*2+1];
                        float aZ0 = acc[1][mi][ni][hh*2+0], aZ1 = acc[1][mi][ni][hh*2+1];
                        float aN0 = acc[2][mi][ni][hh*2+0], aN1 = acc[2][mi][ni][hh*2+1];

                        float2 hp = *(float2*)&g_h[(size_t)(gru*1024 + b)*HP + j];
                        float r0 = sigmoidf_(xw0[0] + aR0);
                        float r1 = sigmoidf_(xw1[0] + aR1);
                        float z0 = sigmoidf_(xw0[1] + aZ0);
                        float z1 = sigmoidf_(xw1[1] + aZ1);
                        float n0 = tanhf(xw0[2] + r0*(aN0 + bn0));
                        float n1 = tanhf(xw1[2] + r1*(aN1 + bn1));
                        float h0 = (1.f - z0)*n0 + z0*hp.x;
                        float h1 = (1.f - z1)*n1 + z1*hp.y;

                        *(float2*)&g_h[(size_t)(gru*1024 + b)*HP + j] = make_float2(h0, h1);

                        __half2 hi2 = __floats2half2_rn(h0, h1);
                        __half2 lo2 = __floats2half2_rn(h0 - __low2float(hi2), h1 - __high2float(hi2));
                        uint32_t sw = swz128((uint32_t)(mrow*128 + (j&63)*2));
                        *(__half2*)(g_Ah + a_img(gru, par_w, mt, 0, j>>6) + sw) = hi2;
                        *(__half2*)(g_Ah + a_img(gru, par_w, mt, 1, j>>6) + sw) = lo2;

                        if (gru){
                            *(float2*)&g_hist[((size_t)b*T_ + t)*HP + j] = make_float2(h0, h1);
                        } else {
                            hqS[mrow*65+jj]   = h0;
                            hqS[mrow*65+jj+1] = h1;
                        }
                    }
                }
            }

            // -------- q role: mu/std partials for step t --------
            if (!gru){
                __syncthreads();
                for (int idx = tid; idx < 64*32; idx += 256){
                    int b = idx >> 5, o = idx & 31;
                    float s = 0.f;
#pragma unroll
                    for (int j=0;j<64;j++)
                        s = fmaf(hqS[b*65+j], WqS[j*32+o], s);
                    g_part[t&1][nt][mt*64+b][o] = s;
                }
            }
        }
        grid_barrier(gen);
    }
}

// ----------------------------- post-loop: all reconstructions ----------------
__global__ __launch_bounds__(256)
void recon_all(const float* __restrict__ Wpm, const float* __restrict__ bpm,
               const float* __restrict__ Wps, const float* __restrict__ bps,
               float* __restrict__ out_rm, float* __restrict__ out_rs){
    extern __shared__ float hs[];    // [RROWS][HP]
    int m0 = blockIdx.x * RROWS;
    int tid = threadIdx.x, w = tid>>5, lane = tid&31;
#pragma unroll
    for (int k=0;k<RROWS*128/256;k++){
        int idx = k*256 + tid;
        int r = idx >> 7, q4 = idx & 127;
        ((float4*)&hs[r*HP])[q4] = ((const float4*)&g_hist[(size_t)(m0+r)*HP])[q4];
    }
    __syncthreads();
    for (int o = w; o < 2*XD_; o += 8){
        int d = (o < XD_) ? o : o - XD_;
        const float* Wrow = ((o < XD_) ? Wpm : Wps) + (size_t)d*H_;
        for (int r=0;r<RROWS;r++){
            float acc = 0.f;
            for (int i=lane; i<H_; i+=32) acc = fmaf(hs[r*HP+i], Wrow[i], acc);
#pragma unroll
            for (int off=16; off; off>>=1) acc += __shfl_down_sync(0xFFFFFFFFu, acc, off);
            if (lane == 0){
                size_t oidx = (size_t)(m0+r)*XD_ + d;
                if (o < XD_) out_rm[oidx] = acc + bpm[d];
                else         out_rs[oidx] = softplusf_(acc + bps[d]) + 1e-4f;
            }
        }
    }
}

// ----------------------------- launcher --------------------------------------
extern "C" void kernel_launch(void* const* d_in, const int* in_sizes, int n_in,
                              void* d_out, int out_size){
    const float* x     = (const float*)d_in[0];
    const float* eps   = (const float*)d_in[1];
    const float* Wih_q = (const float*)d_in[2];
    const float* Whh_q = (const float*)d_in[3];
    const float* bih_q = (const float*)d_in[4];
    const float* bhh_q = (const float*)d_in[5];
    const float* Wqm   = (const float*)d_in[6];
    const float* bqm   = (const float*)d_in[7];
    const float* Wqs   = (const float*)d_in[8];
    const float* bqs   = (const float*)d_in[9];
    const float* Wih_p = (const float*)d_in[10];
    const float* Whh_p = (const float*)d_in[11];
    const float* bih_p = (const float*)d_in[12];
    const float* bhh_p = (const float*)d_in[13];
    const float* Wpm   = (const float*)d_in[14];
    const float* bpm   = (const float*)d_in[15];
    const float* Wps   = (const float*)d_in[16];
    const float* bps   = (const float*)d_in[17];
    const float* fu    = (const float*)d_in[18];
    const float* fw    = (const float*)d_in[19];
    const float* fb    = (const float*)d_in[20];

    float* out = (float*)d_out;
    float* out_rm  = out;
    float* out_rs  = out_rm  + (size_t)B_*T_*XD_;
    float* out_z   = out_rs  + (size_t)B_*T_*XD_;
    float* out_mu  = out_z   + (size_t)B_*T_*ZD_;
    float* out_std = out_mu  + (size_t)B_*T_*ZD_;
    float* out_ld  = out_std + (size_t)B_*T_*ZD_;

    cudaFuncSetAttribute(gru_persist, cudaFuncAttributeMaxDynamicSharedMemorySize, SMEM_P);
    cudaFuncSetAttribute(gx_gemm,     cudaFuncAttributeMaxDynamicSharedMemorySize, SMEM_GX);
    cudaFuncSetAttribute(recon_all,   cudaFuncAttributeMaxDynamicSharedMemorySize, SMEM_RC);

    init_kernel<<<1024,256>>>(out_ld, fu, fw);
    stage_whh<<<(2*G3H*H_+255)/256,256>>>(Whh_q, Whh_p);
    stage_x_wih<<<(B_*T_*XD_ + G3H*XD_ + 255)/256,256>>>(x, Wih_q);
    gx_gemm<<<dim3(GXNT, GXMT),256,SMEM_GX>>>(bih_q, bhh_q);

    dim3 pq_grid(NT_G, 32);   // 8 x 32 = 256 CTAs, 2/SM -> all resident
    gru_persist<<<pq_grid,256,SMEM_P>>>(eps, Wih_p, bih_p, bhh_p, bhh_q,
                                        Wqm, bqm, Wqs, bqs, fw, fb,
                                        out_z, out_mu, out_std, out_ld);

    recon_all<<<(B_*T_)/RROWS,256,SMEM_RC>>>(Wpm, bpm, Wps, bps, out_rm, out_rs);
}

// round 12
// speedup vs baseline: 2.7919x; 1.1582x over previous
#include <cuda_runtime.h>
#include <cuda_fp16.h>
#include <math.h>
#include <stdint.h>

#define B_   1024
#define T_   100
#define XD_  38
#define H_   500
#define ZD_  16
#define L_   3
#define G3H  1500
#define HP   512
#define NG   1536
#define MT_G 16
#define NT_G 8
#define CH_  8
#define AIMG 8192
#define BIMG 8192
#define GXMT 800
#define GXNT 24
#define RROWS 32
#define NCTA_P 256
#define SMEM_P   87040
#define SMEM_GX  25600
#define SMEM_RC  65536

// ----------------------------- device scratch --------------------------------
__device__ __align__(1024) float   g_h[(size_t)2*B_*HP];
__device__ __align__(1024) uint8_t g_Ah[(size_t)2*2*MT_G*CH_*AIMG];   // [gru][par][mt][ch]
__device__ __align__(1024) uint8_t g_Bw[(size_t)2*NT_G*3*CH_*BIMG];   // [gru][nt][gate][ch]
__device__ __align__(1024) uint8_t g_Ax[(size_t)GXMT*16384];          // [mt]
__device__ __align__(1024) uint8_t g_Bx[(size_t)GXNT*BIMG];
__device__ __align__(1024) __half  g_Gx[(size_t)B_*T_*NG];
__device__ __align__(1024) float   g_hist[(size_t)B_*T_*HP];
__device__ float g_part[2][NT_G][B_][32];
__device__ float g_uhat[L_*ZD_];
__device__ unsigned g_bar_count;
__device__ volatile unsigned g_bar_gen;

// ----------------------------- helpers ---------------------------------------
__device__ __forceinline__ float sigmoidf_(float x){ return 1.0f/(1.0f+expf(-x)); }
__device__ __forceinline__ float softplusf_(float x){ return (x>20.0f)? x : log1pf(expf(x)); }
__device__ __forceinline__ uint32_t swz128(uint32_t off){ return off ^ ((off>>3)&0x70); }

__device__ __forceinline__ size_t a_img(int gru,int par,int mt,int ch){
    return ((((size_t)gru*2 + par)*MT_G + mt)*CH_ + ch)*AIMG;
}
__device__ __forceinline__ size_t b_img(int gru,int nt,int gate,int ch){
    return ((((size_t)gru*NT_G + nt)*3 + gate)*CH_ + ch)*BIMG;
}
__device__ __forceinline__ uint32_t smem_u32(const void* p){
    uint32_t a;
    asm("{ .reg .u64 t; cvta.to.shared.u64 t, %1; cvt.u32.u64 %0, t; }" : "=r"(a) : "l"(p));
    return a;
}
__device__ __forceinline__ void cp_async16(uint32_t dst, const void* src){
    asm volatile("cp.async.cg.shared.global [%0], [%1], 16;" :: "r"(dst), "l"(src));
}
__device__ __forceinline__ void cp_commit(){ asm volatile("cp.async.commit_group;" ::: "memory"); }
template<int N>
__device__ __forceinline__ void cp_wait(){ asm volatile("cp.async.wait_group %0;" :: "n"(N) : "memory"); }
__device__ __forceinline__ void ldsm_x4(uint32_t& r0, uint32_t& r1, uint32_t& r2, uint32_t& r3, uint32_t addr){
    asm volatile("ldmatrix.sync.aligned.m8n8.x4.shared.b16 {%0,%1,%2,%3}, [%4];"
                 : "=r"(r0), "=r"(r1), "=r"(r2), "=r"(r3) : "r"(addr));
}
__device__ __forceinline__ void mma_fp16(float* c, const uint32_t* a, const uint32_t* b){
    asm volatile("mma.sync.aligned.m16n8k16.row.col.f32.f16.f16.f32 "
                 "{%0,%1,%2,%3}, {%4,%5,%6,%7}, {%8,%9}, {%0,%1,%2,%3};"
                 : "+f"(c[0]), "+f"(c[1]), "+f"(c[2]), "+f"(c[3])
                 : "r"(a[0]), "r"(a[1]), "r"(a[2]), "r"(a[3]), "r"(b[0]), "r"(b[1]));
}
__device__ __forceinline__ void grid_barrier(unsigned &gen){
    __syncthreads();
    gen++;
    if (threadIdx.x == 0){
        __threadfence();
        unsigned prev = atomicAdd(&g_bar_count, 1u);
        if (prev == gen*NCTA_P - 1u){
            __threadfence();
            g_bar_gen = gen;
        } else {
            while (g_bar_gen < gen) __nanosleep(64);
        }
    }
    __syncthreads();
    __threadfence();
}

// ----------------------------- setup launch 1: init --------------------------
__global__ void init_kernel(float* __restrict__ out_ld,
                            const float* __restrict__ fu, const float* __restrict__ fw){
    size_t i = (size_t)blockIdx.x*blockDim.x + threadIdx.x;
    size_t stride = (size_t)gridDim.x*blockDim.x;
    float4* h4 = (float4*)g_h;
    for (size_t k=i; k<sizeof(g_h)/16;  k+=stride) h4[k] = make_float4(0,0,0,0);
    uint4* p;
    p = (uint4*)g_Ah; for (size_t k=i; k<sizeof(g_Ah)/16; k+=stride) p[k] = make_uint4(0,0,0,0);
    p = (uint4*)g_Bw; for (size_t k=i; k<sizeof(g_Bw)/16; k+=stride) p[k] = make_uint4(0,0,0,0);
    p = (uint4*)g_Ax; for (size_t k=i; k<sizeof(g_Ax)/16; k+=stride) p[k] = make_uint4(0,0,0,0);
    p = (uint4*)g_Bx; for (size_t k=i; k<sizeof(g_Bx)/16; k+=stride) p[k] = make_uint4(0,0,0,0);
    for (size_t k=i; k<B_; k+=stride) out_ld[k]=0.f;
    if (i == 0){ g_bar_count = 0; g_bar_gen = 0; }
    if (i < L_){
        int k = (int)i;
        float wu=0.f, ww=0.f;
        for (int j=0;j<ZD_;j++){ wu += fw[k*ZD_+j]*fu[k*ZD_+j]; ww += fw[k*ZD_+j]*fw[k*ZD_+j]; }
        float m = -1.0f + softplusf_(wu);
        float scale = (m - wu)/(ww + 1e-6f);
        for (int j=0;j<ZD_;j++) g_uhat[k*ZD_+j] = fu[k*ZD_+j] + scale*fw[k*ZD_+j];
    }
}

// ----------------------------- setup launch 2: stage both Whh ----------------
__global__ void stage_whh(const float* __restrict__ Wq, const float* __restrict__ Wp){
    int idx = blockIdx.x*blockDim.x + threadIdx.x;
    if (idx >= 2*G3H*H_) return;
    int gru = idx / (G3H*H_);
    int rem = idx - gru*(G3H*H_);
    int n = rem / H_, k = rem - n*H_;
    float v = (gru ? Wp : Wq)[n*H_ + k];
    int gate = n / 500, j = n - gate*500;
    int nt = j>>6, r = j&63, ch = k>>6, c = k&63;
    *(__half*)(g_Bw + b_img(gru,nt,gate,ch) + swz128((uint32_t)(r*128 + c*2))) = __float2half_rn(v);
}

// ----------------------------- setup launch 3: stage x + Wih_q ---------------
__global__ void stage_x_wih(const float* __restrict__ x, const float* __restrict__ Wih_q){
    int idx = blockIdx.x*blockDim.x + threadIdx.x;
    const int NX = B_*T_*XD_;
    if (idx < NX){
        int m = idx / XD_, d = idx - m*XD_;
        int mt = m>>7, r = m&127;
        uint32_t sw = swz128((uint32_t)(r*128 + d*2));
        *(__half*)(g_Ax + (size_t)mt*16384 + sw) = __float2half_rn(x[idx]);
    } else if (idx < NX + G3H*XD_){
        int e = idx - NX;
        int n = e / XD_, d = e - n*XD_;
        int gate = n / 500, j = n - gate*500;
        int ni = gate*512 + j;
        int nt = ni>>6, r = ni&63;
        *(__half*)(g_Bx + (size_t)nt*BIMG + swz128((uint32_t)(r*128 + d*2))) =
            __float2half_rn(Wih_q[n*XD_ + d]);
    }
}

// ----------------------------- setup launch 4: Gx = x @ Wih_q^T + bias -------
__global__ __launch_bounds__(256)
void gx_gemm(const float* __restrict__ bih, const float* __restrict__ bhh){
    extern __shared__ uint8_t smem_raw[];
    uint8_t* tiles = (uint8_t*)(((uintptr_t)smem_raw + 1023) & ~(uintptr_t)1023);
    uint32_t sbase = smem_u32(tiles);
    int tid = threadIdx.x, wid = tid>>5, lane = tid&31;
    int nt = blockIdx.x, mt = blockIdx.y;
    int wm = wid & 1, wn = wid >> 1;

    {
        const uint8_t* sa = g_Ax + (size_t)mt*16384;
        const uint8_t* sb = g_Bx + (size_t)nt*BIMG;
#pragma unroll
        for (int r=0;r<6;r++){
            int idx = r*256 + tid;         // 0..1535
            if (idx < 1024) cp_async16(sbase + idx*16, sa + idx*16);
            else            cp_async16(sbase + 16384 + (idx-1024)*16, sb + (idx-1024)*16);
        }
    }
    cp_commit(); cp_wait<0>(); __syncthreads();

    float acc[4][2][4];
#pragma unroll
    for (int i=0;i<4;i++)
#pragma unroll
        for (int j=0;j<2;j++)
#pragma unroll
            for (int c=0;c<4;c++) acc[i][j][c]=0.f;

    int g = lane >> 3, l = lane & 7;
    int a_row = wm*64 + (g&1)*8 + l;
    int a_kb  = (g>>1)*16;
    int b_row = wn*16 + (g>>1)*8 + l;
    int b_kb  = (g&1)*16;

#pragma unroll
    for (int s=0; s<4; s++){
        uint32_t Ah[4][4], Bf[2][2];
        uint32_t a_off = swz128((uint32_t)(a_row*128 + s*32 + a_kb));
        uint32_t b_off = swz128((uint32_t)(b_row*128 + s*32 + b_kb));
#pragma unroll
        for (int mi=0; mi<4; mi++)
            ldsm_x4(Ah[mi][0],Ah[mi][1],Ah[mi][2],Ah[mi][3], sbase + a_off + mi*2048);
        {
            uint32_t r0,r1,r2,r3;
            ldsm_x4(r0,r1,r2,r3, sbase + 16384 + b_off);
            Bf[0][0]=r0; Bf[0][1]=r1; Bf[1][0]=r2; Bf[1][1]=r3;
        }
#pragma unroll
        for (int mi=0; mi<4; mi++)
#pragma unroll
            for (int ni=0; ni<2; ni++)
                mma_fp16(acc[mi][ni], Ah[mi], Bf[ni]);
    }

    int rr = lane>>2, cc = (lane&3)*2;
#pragma unroll
    for (int mi=0; mi<4; mi++){
#pragma unroll
        for (int ni=0; ni<2; ni++){
#pragma unroll
            for (int hh=0; hh<2; hh++){
                int m = mt*128 + wm*64 + mi*16 + hh*8 + rr;
                int n = nt*64 + wn*16 + ni*8 + cc;
                int gate = n>>9, j = n&511;
                float v0 = acc[mi][ni][hh*2+0];
                float v1 = acc[mi][ni][hh*2+1];
                if (j+1 < 500){
                    float b0 = bih[gate*500+j]   + (gate<2 ? bhh[gate*500+j]   : 0.f);
                    float b1 = bih[gate*500+j+1] + (gate<2 ? bhh[gate*500+j+1] : 0.f);
                    v0 += b0; v1 += b1;
                }
                *(__half2*)&g_Gx[(size_t)m*NG + n] = __floats2half2_rn(v0, v1);
            }
        }
    }
}

// ----------------------------- persistent stepped kernel ---------------------
// grid (8, 32): y<16 -> p-role (gru=1), y>=16 -> q-role (gru=0).
// iteration it: p runs t=it (it>=0), q runs t=it+1 (it+1<T). Grid barrier per it.
__global__ __launch_bounds__(256,2)
void gru_persist(const float* __restrict__ eps,
                 const float* __restrict__ Wihp,
                 const float* __restrict__ bihp, const float* __restrict__ bhhp,
                 const float* __restrict__ bhhq,
                 const float* __restrict__ Wqm, const float* __restrict__ bqm,
                 const float* __restrict__ Wqs, const float* __restrict__ bqs,
                 const float* __restrict__ fw, const float* __restrict__ fb,
                 float* __restrict__ out_z, float* __restrict__ out_mu,
                 float* __restrict__ out_std, float* __restrict__ out_ld){
    int role = blockIdx.y >> 4;
    int gru  = role ? 0 : 1;            // 1 = p, 0 = q
    int nt = blockIdx.x, mt = blockIdx.y & 15;

    extern __shared__ uint8_t smem_raw[];
    uint8_t* tiles = (uint8_t*)(((uintptr_t)smem_raw + 1023) & ~(uintptr_t)1023);
    uint32_t sbase = smem_u32(tiles);
    // persistent high region (above 2x32KB tile buffers)
    float* zzS  = (float*)(tiles + 65536);   // p: [64][17] per-step
    float* wpS  = (float*)(tiles + 69888);   // p: [16][192] static
    float* bspS = (float*)(tiles + 82176);   // p: [4][64]  static
    float* WzS  = (float*)(tiles + 83200);   // p: [16][32] static
    float* bnnS = (float*)(tiles + 65536);   // q: [64]     static
    float* WqS  = (float*)(tiles + 65792);   // q: [64][32] static

    int tid = threadIdx.x, wid = tid>>5, lane = tid&31;
    int wm = wid & 1, wn = wid >> 1;

    // ---- one-time staging of time-invariant data ----
    if (!gru){
        if (tid < 64){
            int j = nt*64 + tid;
            bnnS[tid] = (j < 500) ? bhhq[1000 + j] : 0.f;
        }
        for (int idx = tid; idx < 64*32; idx += 256){
            int j = idx >> 5, o = idx & 31;
            int gj = nt*64 + j;
            float v = 0.f;
            if (gj < H_)
                v = (o < 16) ? Wqm[o*(H_+ZD_) + gj] : Wqs[(o-16)*(H_+ZD_) + gj];
            WqS[j*32+o] = v;
        }
    } else {
        for (int idx = tid; idx < ZD_*192; idx += 256){
            int d = idx & 15, col = idx >> 4;
            int gg = col >> 6, jj = col & 63;
            int j = nt*64 + jj;
            wpS[d*192 + col] = (j < 500) ? Wihp[((size_t)(gg*500 + j))*ZD_ + d] : 0.f;
        }
        {
            int q4 = tid >> 6, jj = tid & 63;
            int j = nt*64 + jj;
            float v = 0.f;
            if (j < 500){
                if (q4 == 0) v = bihp[j]       + bhhp[j];
                else if (q4 == 1) v = bihp[500+j]  + bhhp[500+j];
                else if (q4 == 2) v = bihp[1000+j];
                else v = bhhp[1000+j];
            }
            bspS[q4*64 + jj] = v;
        }
        for (int idx = tid; idx < 16*32; idx += 256){
            int d = idx >> 5, o = idx & 31;
            WzS[idx] = (o < 16) ? Wqm[o*(H_+ZD_) + H_ + d]
                                : Wqs[(o-16)*(H_+ZD_) + H_ + d];
        }
    }
    __syncthreads();

    int g = lane >> 3, l = lane & 7;
    int a_row = wm*32 + (g&1)*8 + l;
    int a_kb  = (g>>1)*16;
    int b_row = wn*16 + (g>>1)*8 + l;
    int b_kb  = (g&1)*16;
    int rr = lane>>2, cc = (lane&3)*2;

    unsigned gen = 0;

    for (int it = -1; it < T_; ++it){
        int t = gru ? it : (it + 1);
        bool active = gru ? (it >= 0) : (it + 1 < T_);
        if (active){
            int par_w = t & 1;
            int par_r = par_w ^ 1;

            auto copy_chunk = [&](int ch, int buf){
                const uint8_t* srcs[4] = {
                    g_Ah + a_img(gru,par_r,mt,ch),
                    g_Bw + b_img(gru,nt,0,ch), g_Bw + b_img(gru,nt,1,ch), g_Bw + b_img(gru,nt,2,ch)
                };
                uint32_t dbase = sbase + buf*32768;
#pragma unroll
                for (int r=0;r<8;r++){
                    int idx = r*256 + tid;       // 0..2047
                    int img = idx >> 9;          // 0..3
                    int off = (idx & 511)*16;
                    cp_async16(dbase + img*8192 + off, srcs[img] + off);
                }
            };

            copy_chunk(0,0); cp_commit();

            if (gru){
                // ---------- p prologue: z(t) from partials + flows ----------
                float* zpS = (float*)(tiles + 32768);   // [64][16] (buffer-1 scratch)
                float* muS = (float*)(tiles + 36864);   // [64][16]
                float* sdS = (float*)(tiles + 40960);   // [64][16]
                for (int idx = tid; idx < 64*16; idx += 256){
                    int r = idx >> 4, d = idx & 15;
                    zpS[idx] = (t==0) ? 0.f : out_z[((size_t)(mt*64+r)*T_ + (t-1))*ZD_ + d];
                }
                __syncthreads();
                for (int idx = tid; idx < 64*32; idx += 256){
                    int b = idx >> 5, o = idx & 31;
                    int gb = mt*64 + b;
                    float s = 0.f;
#pragma unroll
                    for (int q8 = 0; q8 < NT_G; q8++) s += g_part[t&1][q8][gb][o];
#pragma unroll
                    for (int d = 0; d < ZD_; d++) s = fmaf(zpS[b*16+d], WzS[d*32+o], s);
                    if (o < 16){
                        float mu = s + bqm[o];
                        muS[b*16+o] = mu;
                        if (nt == 0) out_mu[((size_t)gb*T_+t)*ZD_+o] = mu;
                    } else {
                        int oj = o - 16;
                        float sd = softplusf_(s + bqs[oj]) + 1e-4f;
                        sdS[b*16+oj] = sd;
                        if (nt == 0) out_std[((size_t)gb*T_+t)*ZD_+oj] = sd;
                    }
                }
                __syncthreads();
                if (tid < 64){
                    int b = tid, gb = mt*64 + b;
                    float z[ZD_];
#pragma unroll
                    for (int d=0; d<ZD_; d++)
                        z[d] = muS[b*16+d] + eps[((size_t)gb*T_+t)*ZD_+d]*sdS[b*16+d];
                    float ld = 0.f;
#pragma unroll
                    for (int k=0;k<L_;k++){
                        float dot = 0.f;
                        for (int i=0;i<ZD_;i++) dot = fmaf(z[i], fw[k*ZD_+i], dot);
                        float hh = tanhf(dot + fb[k]);
                        float psiu = 0.f;
                        for (int i=0;i<ZD_;i++){
                            z[i] += g_uhat[k*ZD_+i]*hh;
                            psiu = fmaf((1.f - hh*hh)*fw[k*ZD_+i], g_uhat[k*ZD_+i], psiu);
                        }
                        ld += logf(fabsf(1.f + psiu) + 1e-6f);
                    }
#pragma unroll
                    for (int d=0; d<ZD_; d++) zzS[b*17+d] = z[d];
                    if (nt == 0){
#pragma unroll
                        for (int d=0; d<ZD_; d++) out_z[((size_t)gb*T_+t)*ZD_+d] = z[d];
                        out_ld[gb] += ld;
                    }
                }
            }
            __syncthreads();

            float acc[3][2][2][4];
#pragma unroll
            for (int a=0;a<3;a++)
#pragma unroll
                for (int i=0;i<2;i++)
#pragma unroll
                    for (int j=0;j<2;j++)
#pragma unroll
                        for (int c=0;c<4;c++) acc[a][i][j][c]=0.f;

            for (int ch=0; ch<CH_; ch++){
                if (ch+1 < CH_){ copy_chunk(ch+1,(ch+1)&1); cp_commit(); cp_wait<1>(); }
                else cp_wait<0>();
                __syncthreads();

                uint32_t Ahi_b = sbase + (ch&1)*32768;
                uint32_t Bb    = Ahi_b + 8192;

#pragma unroll
                for (int s=0; s<4; s++){
                    uint32_t Ah[2][4], Bf[3][2][2];
                    uint32_t a_off = swz128((uint32_t)(a_row*128 + s*32 + a_kb));
                    uint32_t b_off = swz128((uint32_t)(b_row*128 + s*32 + b_kb));
#pragma unroll
                    for (int mi=0; mi<2; mi++)
                        ldsm_x4(Ah[mi][0],Ah[mi][1],Ah[mi][2],Ah[mi][3], Ahi_b + a_off + mi*2048);
#pragma unroll
                    for (int g3=0; g3<3; g3++){
                        uint32_t r0,r1,r2,r3;
                        ldsm_x4(r0,r1,r2,r3, Bb + g3*8192 + b_off);
                        Bf[g3][0][0]=r0; Bf[g3][0][1]=r1; Bf[g3][1][0]=r2; Bf[g3][1][1]=r3;
                    }
#pragma unroll
                    for (int g3=0; g3<3; g3++)
#pragma unroll
                        for (int mi=0; mi<2; mi++)
#pragma unroll
                            for (int ni=0; ni<2; ni++)
                                mma_fp16(acc[g3][mi][ni], Ah[mi], Bf[g3][ni]);
                }
                __syncthreads();
            }

            // -------- epilogue: GRU combine in registers --------
            float* hqS = (float*)tiles;              // q: [64][65]
#pragma unroll
            for (int mi=0; mi<2; mi++){
#pragma unroll
                for (int hh=0; hh<2; hh++){
                    int mrow = wm*32 + mi*16 + hh*8 + rr;
                    int b = mt*64 + mrow;
                    float zr[ZD_];
                    if (gru){
#pragma unroll
                        for (int d=0; d<ZD_; d++) zr[d] = zzS[mrow*17 + d];
                    }
#pragma unroll
                    for (int ni=0; ni<2; ni++){
                        int jj = wn*16 + ni*8 + cc;
                        int j = nt*64 + jj;
                        if (j >= 500){
                            if (!gru){ hqS[mrow*65+jj] = 0.f; hqS[mrow*65+jj+1] = 0.f; }
                            continue;
                        }
                        float xw0[3], xw1[3];
                        if (!gru){
                            size_t base = ((size_t)b*T_ + t)*NG + j;
#pragma unroll
                            for (int g3=0; g3<3; g3++){
                                __half2 hv = *(const __half2*)&g_Gx[base + g3*512];
                                xw0[g3] = __low2float(hv);
                                xw1[g3] = __high2float(hv);
                            }
                        } else {
#pragma unroll
                            for (int g3=0; g3<3; g3++){
                                float s0 = bspS[g3*64 + jj];
                                float s1 = bspS[g3*64 + jj + 1];
#pragma unroll
                                for (int d=0; d<ZD_; d++){
                                    float zv = zr[d];
                                    s0 = fmaf(zv, wpS[d*192 + g3*64 + jj],     s0);
                                    s1 = fmaf(zv, wpS[d*192 + g3*64 + jj + 1], s1);
                                }
                                xw0[g3] = s0; xw1[g3] = s1;
                            }
                        }
                        float bn0 = gru ? bspS[3*64 + jj]     : bnnS[jj];
                        float bn1 = gru ? bspS[3*64 + jj + 1] : bnnS[jj + 1];
                        float aR0 = acc[0][mi][ni][hh*2+0], aR1 = acc[0][mi][ni][hh*2+1];
                        float aZ0 = acc[1][mi][ni][hh*2+0], aZ1 = acc[1][mi][ni][hh*2+1];
                        float aN0 = acc[2][mi][ni][hh*2+0], aN1 = acc[2][mi][ni][hh*2+1];

                        float2 hp = *(float2*)&g_h[(size_t)(gru*1024 + b)*HP + j];
                        float r0 = sigmoidf_(xw0[0] + aR0);
                        float r1 = sigmoidf_(xw1[0] + aR1);
                        float z0 = sigmoidf_(xw0[1] + aZ0);
                        float z1 = sigmoidf_(xw1[1] + aZ1);
                        float n0 = tanhf(xw0[2] + r0*(aN0 + bn0));
                        float n1 = tanhf(xw1[2] + r1*(aN1 + bn1));
                        float h0 = (1.f - z0)*n0 + z0*hp.x;
                        float h1 = (1.f - z1)*n1 + z1*hp.y;

                        *(float2*)&g_h[(size_t)(gru*1024 + b)*HP + j] = make_float2(h0, h1);

                        __half2 hi2 = __floats2half2_rn(h0, h1);
                        uint32_t sw = swz128((uint32_t)(mrow*128 + (j&63)*2));
                        *(__half2*)(g_Ah + a_img(gru, par_w, mt, j>>6) + sw) = hi2;

                        if (gru){
                            *(float2*)&g_hist[((size_t)b*T_ + t)*HP + j] = make_float2(h0, h1);
                        } else {
                            hqS[mrow*65+jj]   = h0;
                            hqS[mrow*65+jj+1] = h1;
                        }
                    }
                }
            }

            // -------- q role: mu/std partials for step t --------
            if (!gru){
                __syncthreads();
                for (int idx = tid; idx < 64*32; idx += 256){
                    int b = idx >> 5, o = idx & 31;
                    float s = 0.f;
#pragma unroll
                    for (int j=0;j<64;j++)
                        s = fmaf(hqS[b*65+j], WqS[j*32+o], s);
                    g_part[t&1][nt][mt*64+b][o] = s;
                }
            }
        }
        grid_barrier(gen);
    }
}

// ----------------------------- post-loop: all reconstructions ----------------
__global__ __launch_bounds__(256)
void recon_all(const float* __restrict__ Wpm, const float* __restrict__ bpm,
               const float* __restrict__ Wps, const float* __restrict__ bps,
               float* __restrict__ out_rm, float* __restrict__ out_rs){
    extern __shared__ float hs[];    // [RROWS][HP]
    int m0 = blockIdx.x * RROWS;
    int tid = threadIdx.x, w = tid>>5, lane = tid&31;
#pragma unroll
    for (int k=0;k<RROWS*128/256;k++){
        int idx = k*256 + tid;
        int r = idx >> 7, q4 = idx & 127;
        ((float4*)&hs[r*HP])[q4] = ((const float4*)&g_hist[(size_t)(m0+r)*HP])[q4];
    }
    __syncthreads();
    for (int o = w; o < 2*XD_; o += 8){
        int d = (o < XD_) ? o : o - XD_;
        const float* Wrow = ((o < XD_) ? Wpm : Wps) + (size_t)d*H_;
        for (int r=0;r<RROWS;r++){
            float acc = 0.f;
            for (int i=lane; i<H_; i+=32) acc = fmaf(hs[r*HP+i], Wrow[i], acc);
#pragma unroll
            for (int off=16; off; off>>=1) acc += __shfl_down_sync(0xFFFFFFFFu, acc, off);
            if (lane == 0){
                size_t oidx = (size_t)(m0+r)*XD_ + d;
                if (o < XD_) out_rm[oidx] = acc + bpm[d];
                else         out_rs[oidx] = softplusf_(acc + bps[d]) + 1e-4f;
            }
        }
    }
}

// ----------------------------- launcher --------------------------------------
extern "C" void kernel_launch(void* const* d_in, const int* in_sizes, int n_in,
                              void* d_out, int out_size){
    const float* x     = (const float*)d_in[0];
    const float* eps   = (const float*)d_in[1];
    const float* Wih_q = (const float*)d_in[2];
    const float* Whh_q = (const float*)d_in[3];
    const float* bih_q = (const float*)d_in[4];
    const float* bhh_q = (const float*)d_in[5];
    const float* Wqm   = (const float*)d_in[6];
    const float* bqm   = (const float*)d_in[7];
    const float* Wqs   = (const float*)d_in[8];
    const float* bqs   = (const float*)d_in[9];
    const float* Wih_p = (const float*)d_in[10];
    const float* Whh_p = (const float*)d_in[11];
    const float* bih_p = (const float*)d_in[12];
    const float* bhh_p = (const float*)d_in[13];
    const float* Wpm   = (const float*)d_in[14];
    const float* bpm   = (const float*)d_in[15];
    const float* Wps   = (const float*)d_in[16];
    const float* bps   = (const float*)d_in[17];
    const float* fu    = (const float*)d_in[18];
    const float* fw    = (const float*)d_in[19];
    const float* fb    = (const float*)d_in[20];

    float* out = (float*)d_out;
    float* out_rm  = out;
    float* out_rs  = out_rm  + (size_t)B_*T_*XD_;
    float* out_z   = out_rs  + (size_t)B_*T_*XD_;
    float* out_mu  = out_z   + (size_t)B_*T_*ZD_;
    float* out_std = out_mu  + (size_t)B_*T_*ZD_;
    float* out_ld  = out_std + (size_t)B_*T_*ZD_;

    cudaFuncSetAttribute(gru_persist, cudaFuncAttributeMaxDynamicSharedMemorySize, SMEM_P);
    cudaFuncSetAttribute(gx_gemm,     cudaFuncAttributeMaxDynamicSharedMemorySize, SMEM_GX);
    cudaFuncSetAttribute(recon_all,   cudaFuncAttributeMaxDynamicSharedMemorySize, SMEM_RC);

    init_kernel<<<1024,256>>>(out_ld, fu, fw);
    stage_whh<<<(2*G3H*H_+255)/256,256>>>(Whh_q, Whh_p);
    stage_x_wih<<<(B_*T_*XD_ + G3H*XD_ + 255)/256,256>>>(x, Wih_q);
    gx_gemm<<<dim3(GXNT, GXMT),256,SMEM_GX>>>(bih_q, bhh_q);

    dim3 pq_grid(NT_G, 32);   // 8 x 32 = 256 CTAs, 2/SM -> all resident
    gru_persist<<<pq_grid,256,SMEM_P>>>(eps, Wih_p, bih_p, bhh_p, bhh_q,
                                        Wqm, bqm, Wqs, bqs, fw, fb,
                                        out_z, out_mu, out_std, out_ld);

    recon_all<<<(B_*T_)/RROWS,256,SMEM_RC>>>(Wpm, bpm, Wps, bps, out_rm, out_rs);
}